// round 6
// baseline (speedup 1.0000x reference)
#include <cuda_runtime.h>

#define DD 128
#define GG 384
#define BV 256
#define MM 32
#define LL 24
#define NOUT 193
#define NSEQ 9
#define WPAD 132

typedef unsigned long long u64;

// ---------------- scratch (static device globals; no allocation) -------------
__device__ float g_e3[3 * BV * DD];            // cond/proc/drug visit embeddings
__device__ float g_mon[2 * BV * MM * DD];      // lab / inj monitor embeddings
__device__ float g_xg34[2 * BV * MM * GG];     // monitor input-gates, keys 3,4
__device__ float g_xg012[3 * BV * GG];         // monitor input-gates, keys 0-2 (t-invariant)
__device__ float g_h5[5 * BV * DD];            // monitor final hidden
__device__ float g_vxg[7 * 16 * 16 * GG];      // visit input-gates
__device__ float g_hv[7 * 16 * DD];            // visit final hidden
__device__ float g_wT[24 * DD * GG];           // transposed weights [d][g]

#define WIH_M 0
#define WHH_M (5 * DD * GG)
#define WIH_V (10 * DD * GG)
#define WHH_V (17 * DD * GG)

__device__ __forceinline__ float sigf(float x) { return 1.0f / (1.0f + __expf(-x)); }

// f32x2 packed helpers (Blackwell)
__device__ __forceinline__ u64 pack_lo(float x) {
    u64 r; asm("mov.b64 %0, {%1, %2};" : "=l"(r) : "f"(x), "f"(0.0f)); return r;
}
__device__ __forceinline__ void ffma2(u64& acc, u64 a, u64 b) {
    asm("fma.rn.f32x2 %0, %1, %2, %0;" : "+l"(acc) : "l"(a), "l"(b));
}
__device__ __forceinline__ float hsum2(u64 a) {
    float lo, hi; asm("mov.b64 {%0, %1}, %2;" : "=f"(lo), "=f"(hi) : "l"(a));
    return lo + hi;
}

// ---------------- K0: transpose all GRU weights to [d][g] --------------------
__global__ void k_transpose(const float* mih, const float* mhh,
                            const float* vih, const float* vhh) {
    int y = blockIdx.y;      // 0..23: which (tensor,key)
    int g = blockIdx.x;      // 0..383
    int d = threadIdx.x;     // 0..127
    const float* src; int k;
    if (y < 5)       { src = mih; k = y; }
    else if (y < 10) { src = mhh; k = y - 5; }
    else if (y < 17) { src = vih; k = y - 10; }
    else             { src = vhh; k = y - 17; }
    g_wT[y * (DD * GG) + d * GG + g] = src[(k * GG + g) * DD + d];
}

// ---------------- K1: visit-event embedding sums ------------------------------
__global__ void k_embed_visit(const int* tc, const int* tp, const int* td,
                              const float* ec, const float* ep, const float* ed) {
    int n = blockIdx.x, key = blockIdx.y, d = threadIdx.x;
    const int* tok = (key == 0) ? tc : (key == 1) ? tp : td;
    const float* emb = (key == 0) ? ec : (key == 1) ? ep : ed;
    float acc = 0.f;
#pragma unroll
    for (int l = 0; l < LL; l++) acc += emb[tok[n * LL + l] * DD + d];
    g_e3[(key * BV + n) * DD + d] = acc;
}

// ---------------- K2: monitor-event pair embedding sums (float4) -------------
__global__ void k_embed_mon(const int* __restrict__ tli, const int* __restrict__ tlv,
                            const int* __restrict__ tii, const int* __restrict__ tiv,
                            const float* __restrict__ eli, const float* __restrict__ elv,
                            const float* __restrict__ eii, const float* __restrict__ eiv) {
    int pair = blockIdx.y;
    int r = blockIdx.x * 4 + (threadIdx.x >> 5);   // monitor row 0..8191
    int lane = threadIdx.x & 31;
    const int* ti = pair ? tii : tli;
    const int* tv = pair ? tiv : tlv;
    const float4* ei = (const float4*)(pair ? eii : eli);
    const float4* ev = (const float4*)(pair ? eiv : elv);
    float4 acc = make_float4(0.f, 0.f, 0.f, 0.f);
#pragma unroll
    for (int l = 0; l < LL; l++) {
        int a = ti[r * LL + l];
        int b = tv[r * LL + l];
        float4 x = ei[a * 32 + lane];
        float4 y = ev[b * 32 + lane];
        acc.x += x.x * y.x; acc.y += x.y * y.y;
        acc.z += x.z * y.z; acc.w += x.w * y.w;
    }
    ((float4*)g_mon)[(pair * 8192 + r) * 32 + lane] = acc;
}

// ---------------- K3a: monitor input-gates for keys 3,4 (R2 version) ----------
__global__ void __launch_bounds__(384) k_xg34(const float* bih) {
    __shared__ float sx[DD * 36];   // x transposed [d][t], pad 4 (16B-aligned rows)
    int pair = blockIdx.y, n = blockIdx.x, key = 3 + pair;
    int g = threadIdx.x;
    for (int i = g; i < MM * DD; i += GG) {
        int t = i / DD, d = i % DD;
        sx[d * 36 + t] = g_mon[((pair * BV + n) * MM + t) * DD + d];
    }
    __syncthreads();
    float b = bih[key * GG + g];
    float acc[MM];
#pragma unroll
    for (int t = 0; t < MM; t++) acc[t] = b;
    const float* w = &g_wT[WIH_M + key * (DD * GG) + g];
    for (int d = 0; d < DD; d++) {
        float wv = w[d * GG];
        const float4* x4 = (const float4*)&sx[d * 36];
#pragma unroll
        for (int q = 0; q < 8; q++) {
            float4 x = x4[q];
            acc[q * 4 + 0] += wv * x.x; acc[q * 4 + 1] += wv * x.y;
            acc[q * 4 + 2] += wv * x.z; acc[q * 4 + 3] += wv * x.w;
        }
    }
    float* out = &g_xg34[((pair * BV + n) * MM) * GG + g];
#pragma unroll
    for (int t = 0; t < MM; t++) out[t * GG] = acc[t];
}

// ---------------- K3b: monitor input-gates for keys 0-2 (t-invariant) --------
__global__ void k_xg012(const float* bih) {
    __shared__ float sx[DD];
    int key = blockIdx.y, n = blockIdx.x, g = threadIdx.x;
    if (g < DD) sx[g] = g_e3[(key * BV + n) * DD + g];
    __syncthreads();
    float acc = bih[key * GG + g];
    const float* w = &g_wT[WIH_M + key * (DD * GG) + g];
#pragma unroll 4
    for (int d = 0; d < DD; d++) acc += w[d * GG] * sx[d];
    g_xg012[(key * BV + n) * GG + g] = acc;
}

// ---------------- K4: monitor GRU recurrence — W [g][d] pad132, FFMA2 ---------
// grid (29, 5), block 384, dyn smem = (GG*WPAD + NSEQ*DD + NSEQ*GG)*4 = 221184 B
__global__ void __launch_bounds__(384) k_mon_gru(const float* __restrict__ whh,
                                                 const float* __restrict__ bhh) {
    extern __shared__ float sm[];
    float* s_w = sm;                       // [384][132]  202752 B
    float* s_h = sm + GG * WPAD;           // [9][128]      4608 B
    float* s_gh = s_h + NSEQ * DD;         // [9][384]     13824 B
    int key = blockIdx.y, grp = blockIdx.x, g = threadIdx.x;
    int n0 = grp * NSEQ;
    int ns = min(NSEQ, BV - n0);
    // whh is already [g][d] row-major per key; coalesced copy into padded rows
    for (int i = g; i < GG * DD; i += GG) {
        int row = i >> 7, col = i & 127;
        s_w[row * WPAD + col] = whh[key * (GG * DD) + i];
    }
    for (int i = g; i < NSEQ * DD; i += GG) s_h[i] = 0.f;
    __syncthreads();
    float bb = bhh[key * GG + g];
    int ss = g >> 7, dd = g & 127;
    const ulonglong2* wrow = (const ulonglong2*)(s_w + g * WPAD);
    for (int t = 0; t < MM; t++) {
        u64 acc[NSEQ];
#pragma unroll
        for (int s = 0; s < NSEQ; s++) acc[s] = pack_lo(s == 0 ? bb : 0.0f);
#pragma unroll 4
        for (int dc = 0; dc < 32; dc++) {
            ulonglong2 w4 = wrow[dc];
#pragma unroll
            for (int s = 0; s < NSEQ; s++) {
                ulonglong2 h4 = *(const ulonglong2*)(s_h + s * DD + dc * 4);
                ffma2(acc[s], w4.x, h4.x);
                ffma2(acc[s], w4.y, h4.y);
            }
        }
        {
            float g0 = hsum2(acc[0]);            // includes bias
            s_gh[0 * GG + g] = g0;
#pragma unroll
            for (int s = 1; s < NSEQ; s++) s_gh[s * GG + g] = bb + hsum2(acc[s]);
        }
        __syncthreads();
#pragma unroll
        for (int sb = 0; sb < NSEQ; sb += 3) {
            int s = sb + ss;
            if (s < ns) {
                int n = n0 + s;
                const float* xg = (key < 3)
                    ? &g_xg012[(key * BV + n) * GG]
                    : &g_xg34[(((key - 3) * BV + n) * MM + t) * GG];
                float ghr = s_gh[s * GG + dd];
                float ghz = s_gh[s * GG + DD + dd];
                float ghn = s_gh[s * GG + 2 * DD + dd];
                float h = s_h[s * DD + dd];
                float r = sigf(xg[dd] + ghr);
                float z = sigf(xg[DD + dd] + ghz);
                float nn = tanhf(xg[2 * DD + dd] + r * ghn);
                s_h[s * DD + dd] = (1.f - z) * nn + z * h;
            }
        }
        __syncthreads();
    }
    for (int i = g; i < ns * DD; i += GG) g_h5[(key * BV + n0) * DD + i] = s_h[i];
}

// ---------------- K5: visit input-gates (R2 version) ---------------------------
__global__ void __launch_bounds__(384) k_vxg(const float* weight, const float* age,
                                             const float* info_w, const float* info_b,
                                             const float* bih) {
    __shared__ float sx[16 * DD];
    int key = blockIdx.y, b = blockIdx.x, g = threadIdx.x;
    for (int i = g; i < 16 * DD; i += GG) {
        int v = i / DD, d = i % DD;
        float x;
        if (key < 5)       x = g_h5[(key * BV + b * 16 + v) * DD + d];
        else if (key == 5) x = weight[b * 16 + v] * info_w[d] + info_b[d];
        else               x = age[b * 16 + v] * info_w[DD + d] + info_b[DD + d];
        sx[i] = x;
    }
    __syncthreads();
    float bb = bih[key * GG + g];
    float acc[16];
#pragma unroll
    for (int v = 0; v < 16; v++) acc[v] = bb;
    const float* w = &g_wT[WIH_V + key * (DD * GG) + g];
    for (int d = 0; d < DD; d++) {
        float wv = w[d * GG];
#pragma unroll
        for (int v = 0; v < 16; v++) acc[v] += wv * sx[v * DD + d];
    }
    float* out = &g_vxg[((key * 16 + b) * 16) * GG + g];
#pragma unroll
    for (int v = 0; v < 16; v++) out[v * GG] = acc[v];
}

// ---------------- K6: visit GRU recurrence -------------------------------------
// grid (16, 7), block 384, dyn smem = (DD*GG + DD + GG)*4 = 198656 B
__global__ void __launch_bounds__(384) k_vis_gru(const float* bhh) {
    extern __shared__ float sm[];
    float* s_w = sm;
    float* s_h = sm + DD * GG;
    float* s_gh = s_h + DD;
    int key = blockIdx.y, b = blockIdx.x, g = threadIdx.x;
    for (int i = g; i < DD * GG; i += GG) s_w[i] = g_wT[WHH_V + key * (DD * GG) + i];
    if (g < DD) s_h[g] = 0.f;
    __syncthreads();
    float bb = bhh[key * GG + g];
    for (int t = 0; t < 16; t++) {
        float acc = bb;
#pragma unroll 4
        for (int d = 0; d < DD; d++) acc += s_w[d * GG + g] * s_h[d];
        s_gh[g] = acc;
        __syncthreads();
        if (g < DD) {
            const float* xg = &g_vxg[((key * 16 + b) * 16 + t) * GG];
            float r = sigf(xg[g] + s_gh[g]);
            float z = sigf(xg[DD + g] + s_gh[DD + g]);
            float nn = tanhf(xg[2 * DD + g] + r * s_gh[2 * DD + g]);
            s_h[g] = (1.f - z) * nn + z * s_h[g];
        }
        __syncthreads();
    }
    if (g < DD) g_hv[(key * 16 + b) * DD + g] = s_h[g];
}

// ---------------- K7: ReLU + final FC --------------------------------------------
__global__ void k_fc(const float* fcw, const float* fcb, float* out) {
    __shared__ float pe[7 * DD];
    int b = blockIdx.x, o = threadIdx.x;
    for (int i = o; i < 7 * DD; i += 256) {
        int k = i / DD, d = i % DD;
        pe[i] = fmaxf(g_hv[(k * 16 + b) * DD + d], 0.f);
    }
    __syncthreads();
    if (o < NOUT) {
        float acc = fcb[o];
        for (int j = 0; j < 7 * DD; j++) acc += pe[j] * fcw[j * NOUT + o];
        out[b * NOUT + o] = acc;
    }
}

// ---------------- launch -----------------------------------------------------------
extern "C" void kernel_launch(void* const* d_in, const int* in_sizes, int n_in,
                              void* d_out, int out_size) {
    const int* tok_cond      = (const int*)d_in[0];
    const int* tok_proc      = (const int*)d_in[1];
    const int* tok_drug      = (const int*)d_in[2];
    const int* tok_lab_item  = (const int*)d_in[3];
    const int* tok_lab_value = (const int*)d_in[4];
    const int* tok_inj_item  = (const int*)d_in[5];
    const int* tok_inj_value = (const int*)d_in[6];
    const float* weight      = (const float*)d_in[7];
    const float* age         = (const float*)d_in[8];
    const float* emb_cond    = (const float*)d_in[9];
    const float* emb_proc    = (const float*)d_in[10];
    const float* emb_drug    = (const float*)d_in[11];
    const float* emb_li      = (const float*)d_in[12];
    const float* emb_lv      = (const float*)d_in[13];
    const float* emb_ii      = (const float*)d_in[14];
    const float* emb_iv      = (const float*)d_in[15];
    const float* mgru_wih    = (const float*)d_in[16];
    const float* mgru_whh    = (const float*)d_in[17];
    const float* mgru_bih    = (const float*)d_in[18];
    const float* mgru_bhh    = (const float*)d_in[19];
    const float* vgru_wih    = (const float*)d_in[20];
    const float* vgru_whh    = (const float*)d_in[21];
    const float* vgru_bih    = (const float*)d_in[22];
    const float* vgru_bhh    = (const float*)d_in[23];
    const float* info_w      = (const float*)d_in[24];
    const float* info_b      = (const float*)d_in[25];
    const float* fc_w        = (const float*)d_in[26];
    const float* fc_b        = (const float*)d_in[27];
    float* out = (float*)d_out;

    cudaFuncSetAttribute(k_mon_gru, cudaFuncAttributeMaxDynamicSharedMemorySize, 221184);
    cudaFuncSetAttribute(k_vis_gru, cudaFuncAttributeMaxDynamicSharedMemorySize, 198656);

    k_transpose<<<dim3(384, 24), 128>>>(mgru_wih, mgru_whh, vgru_wih, vgru_whh);
    k_embed_visit<<<dim3(256, 3), 128>>>(tok_cond, tok_proc, tok_drug,
                                         emb_cond, emb_proc, emb_drug);
    k_embed_mon<<<dim3(2048, 2), 128>>>(tok_lab_item, tok_lab_value,
                                        tok_inj_item, tok_inj_value,
                                        emb_li, emb_lv, emb_ii, emb_iv);
    k_xg34<<<dim3(256, 2), 384>>>(mgru_bih);
    k_xg012<<<dim3(256, 3), 384>>>(mgru_bih);
    k_mon_gru<<<dim3(29, 5), 384, 221184>>>(mgru_whh, mgru_bhh);
    k_vxg<<<dim3(16, 7), 384>>>(weight, age, info_w, info_b, vgru_bih);
    k_vis_gru<<<dim3(16, 7), 384, 198656>>>(vgru_bhh);
    k_fc<<<16, 256>>>(fc_w, fc_b, out);
}

// round 7
// speedup vs baseline: 1.0029x; 1.0029x over previous
#include <cuda_runtime.h>

#define DD 128
#define GG 384
#define BV 256
#define MM 32
#define LL 24
#define NOUT 193
#define NSEQ 9
#define WPAD 132

typedef unsigned long long u64;

// ---------------- scratch (static device globals; no allocation) -------------
__device__ float g_e3[3 * BV * DD];            // cond/proc/drug visit embeddings
__device__ float g_mon[2 * BV * MM * DD];      // lab / inj monitor embeddings
__device__ float g_xg34[2 * BV * MM * GG];     // monitor input-gates, keys 3,4
__device__ float g_xg012[3 * BV * GG];         // monitor input-gates, keys 0-2 (t-invariant)
__device__ float g_h5[5 * BV * DD];            // monitor final hidden
__device__ float g_vxg[7 * 16 * 16 * GG];      // visit input-gates
__device__ float g_hv[7 * 16 * DD];            // visit final hidden
__device__ float g_wT[24 * DD * GG];           // transposed weights [d][g]

#define WIH_M 0
#define WHH_M (5 * DD * GG)
#define WIH_V (10 * DD * GG)
#define WHH_V (17 * DD * GG)

__device__ __forceinline__ float sigf(float x) { return 1.0f / (1.0f + __expf(-x)); }

// f32x2 packed helpers (Blackwell)
__device__ __forceinline__ u64 pack_lo(float x) {
    u64 r; asm("mov.b64 %0, {%1, %2};" : "=l"(r) : "f"(x), "f"(0.0f)); return r;
}
__device__ __forceinline__ void ffma2(u64& acc, u64 a, u64 b) {
    asm("fma.rn.f32x2 %0, %1, %2, %0;" : "+l"(acc) : "l"(a), "l"(b));
}
__device__ __forceinline__ float hsum2(u64 a) {
    float lo, hi; asm("mov.b64 {%0, %1}, %2;" : "=f"(lo), "=f"(hi) : "l"(a));
    return lo + hi;
}

// ---------------- K0: transpose all GRU weights to [d][g] --------------------
__global__ void k_transpose(const float* mih, const float* mhh,
                            const float* vih, const float* vhh) {
    int y = blockIdx.y;      // 0..23: which (tensor,key)
    int g = blockIdx.x;      // 0..383
    int d = threadIdx.x;     // 0..127
    const float* src; int k;
    if (y < 5)       { src = mih; k = y; }
    else if (y < 10) { src = mhh; k = y - 5; }
    else if (y < 17) { src = vih; k = y - 10; }
    else             { src = vhh; k = y - 17; }
    g_wT[y * (DD * GG) + d * GG + g] = src[(k * GG + g) * DD + d];
}

// ---------------- K1: visit-event embedding sums ------------------------------
__global__ void k_embed_visit(const int* tc, const int* tp, const int* td,
                              const float* ec, const float* ep, const float* ed) {
    int n = blockIdx.x, key = blockIdx.y, d = threadIdx.x;
    const int* tok = (key == 0) ? tc : (key == 1) ? tp : td;
    const float* emb = (key == 0) ? ec : (key == 1) ? ep : ed;
    float acc = 0.f;
#pragma unroll
    for (int l = 0; l < LL; l++) acc += emb[tok[n * LL + l] * DD + d];
    g_e3[(key * BV + n) * DD + d] = acc;
}

// ---------------- K2: monitor-event pair embedding sums (float4) -------------
__global__ void k_embed_mon(const int* __restrict__ tli, const int* __restrict__ tlv,
                            const int* __restrict__ tii, const int* __restrict__ tiv,
                            const float* __restrict__ eli, const float* __restrict__ elv,
                            const float* __restrict__ eii, const float* __restrict__ eiv) {
    int pair = blockIdx.y;
    int r = blockIdx.x * 4 + (threadIdx.x >> 5);   // monitor row 0..8191
    int lane = threadIdx.x & 31;
    const int* ti = pair ? tii : tli;
    const int* tv = pair ? tiv : tlv;
    const float4* ei = (const float4*)(pair ? eii : eli);
    const float4* ev = (const float4*)(pair ? eiv : elv);
    float4 acc = make_float4(0.f, 0.f, 0.f, 0.f);
#pragma unroll
    for (int l = 0; l < LL; l++) {
        int a = ti[r * LL + l];
        int b = tv[r * LL + l];
        float4 x = ei[a * 32 + lane];
        float4 y = ev[b * 32 + lane];
        acc.x += x.x * y.x; acc.y += x.y * y.y;
        acc.z += x.z * y.z; acc.w += x.w * y.w;
    }
    ((float4*)g_mon)[(pair * 8192 + r) * 32 + lane] = acc;
}

// ---------------- K3a: monitor input-gates for keys 3,4 (R2 version) ----------
__global__ void __launch_bounds__(384) k_xg34(const float* bih) {
    __shared__ float sx[DD * 36];   // x transposed [d][t], pad 4 (16B-aligned rows)
    int pair = blockIdx.y, n = blockIdx.x, key = 3 + pair;
    int g = threadIdx.x;
    for (int i = g; i < MM * DD; i += GG) {
        int t = i / DD, d = i % DD;
        sx[d * 36 + t] = g_mon[((pair * BV + n) * MM + t) * DD + d];
    }
    __syncthreads();
    float b = bih[key * GG + g];
    float acc[MM];
#pragma unroll
    for (int t = 0; t < MM; t++) acc[t] = b;
    const float* w = &g_wT[WIH_M + key * (DD * GG) + g];
    for (int d = 0; d < DD; d++) {
        float wv = w[d * GG];
        const float4* x4 = (const float4*)&sx[d * 36];
#pragma unroll
        for (int q = 0; q < 8; q++) {
            float4 x = x4[q];
            acc[q * 4 + 0] += wv * x.x; acc[q * 4 + 1] += wv * x.y;
            acc[q * 4 + 2] += wv * x.z; acc[q * 4 + 3] += wv * x.w;
        }
    }
    float* out = &g_xg34[((pair * BV + n) * MM) * GG + g];
#pragma unroll
    for (int t = 0; t < MM; t++) out[t * GG] = acc[t];
}

// ---------------- K3b: monitor input-gates for keys 0-2 (t-invariant) --------
__global__ void k_xg012(const float* bih) {
    __shared__ float sx[DD];
    int key = blockIdx.y, n = blockIdx.x, g = threadIdx.x;
    if (g < DD) sx[g] = g_e3[(key * BV + n) * DD + g];
    __syncthreads();
    float acc = bih[key * GG + g];
    const float* w = &g_wT[WIH_M + key * (DD * GG) + g];
#pragma unroll 4
    for (int d = 0; d < DD; d++) acc += w[d * GG] * sx[d];
    g_xg012[(key * BV + n) * GG + g] = acc;
}

// ---------------- K4: monitor GRU recurrence — W [g][d] pad132, FFMA2 ---------
// grid (29, 5), block 384, dyn smem = (GG*WPAD + NSEQ*DD + NSEQ*GG)*4 = 221184 B
__global__ void __launch_bounds__(384) k_mon_gru(const float* __restrict__ whh,
                                                 const float* __restrict__ bhh) {
    extern __shared__ float sm[];
    float* s_w = sm;                       // [384][132]  202752 B
    float* s_h = sm + GG * WPAD;           // [9][128]      4608 B
    float* s_gh = s_h + NSEQ * DD;         // [9][384]     13824 B
    int key = blockIdx.y, grp = blockIdx.x, g = threadIdx.x;
    int n0 = grp * NSEQ;
    int ns = min(NSEQ, BV - n0);
    // whh is already [g][d] row-major per key; coalesced copy into padded rows
    for (int i = g; i < GG * DD; i += GG) {
        int row = i >> 7, col = i & 127;
        s_w[row * WPAD + col] = whh[key * (GG * DD) + i];
    }
    for (int i = g; i < NSEQ * DD; i += GG) s_h[i] = 0.f;
    __syncthreads();
    float bb = bhh[key * GG + g];
    int ss = g >> 7, dd = g & 127;
    const ulonglong2* wrow = (const ulonglong2*)(s_w + g * WPAD);
    for (int t = 0; t < MM; t++) {
        u64 acc[NSEQ];
#pragma unroll
        for (int s = 0; s < NSEQ; s++) acc[s] = pack_lo(s == 0 ? bb : 0.0f);
#pragma unroll 4
        for (int dc = 0; dc < 32; dc++) {
            ulonglong2 w4 = wrow[dc];
#pragma unroll
            for (int s = 0; s < NSEQ; s++) {
                ulonglong2 h4 = *(const ulonglong2*)(s_h + s * DD + dc * 4);
                ffma2(acc[s], w4.x, h4.x);
                ffma2(acc[s], w4.y, h4.y);
            }
        }
        {
            float g0 = hsum2(acc[0]);            // includes bias
            s_gh[0 * GG + g] = g0;
#pragma unroll
            for (int s = 1; s < NSEQ; s++) s_gh[s * GG + g] = bb + hsum2(acc[s]);
        }
        __syncthreads();
#pragma unroll
        for (int sb = 0; sb < NSEQ; sb += 3) {
            int s = sb + ss;
            if (s < ns) {
                int n = n0 + s;
                const float* xg = (key < 3)
                    ? &g_xg012[(key * BV + n) * GG]
                    : &g_xg34[(((key - 3) * BV + n) * MM + t) * GG];
                float ghr = s_gh[s * GG + dd];
                float ghz = s_gh[s * GG + DD + dd];
                float ghn = s_gh[s * GG + 2 * DD + dd];
                float h = s_h[s * DD + dd];
                float r = sigf(xg[dd] + ghr);
                float z = sigf(xg[DD + dd] + ghz);
                float nn = tanhf(xg[2 * DD + dd] + r * ghn);
                s_h[s * DD + dd] = (1.f - z) * nn + z * h;
            }
        }
        __syncthreads();
    }
    for (int i = g; i < ns * DD; i += GG) g_h5[(key * BV + n0) * DD + i] = s_h[i];
}

// ---------------- K5: visit input-gates (R2 version) ---------------------------
__global__ void __launch_bounds__(384) k_vxg(const float* weight, const float* age,
                                             const float* info_w, const float* info_b,
                                             const float* bih) {
    __shared__ float sx[16 * DD];
    int key = blockIdx.y, b = blockIdx.x, g = threadIdx.x;
    for (int i = g; i < 16 * DD; i += GG) {
        int v = i / DD, d = i % DD;
        float x;
        if (key < 5)       x = g_h5[(key * BV + b * 16 + v) * DD + d];
        else if (key == 5) x = weight[b * 16 + v] * info_w[d] + info_b[d];
        else               x = age[b * 16 + v] * info_w[DD + d] + info_b[DD + d];
        sx[i] = x;
    }
    __syncthreads();
    float bb = bih[key * GG + g];
    float acc[16];
#pragma unroll
    for (int v = 0; v < 16; v++) acc[v] = bb;
    const float* w = &g_wT[WIH_V + key * (DD * GG) + g];
    for (int d = 0; d < DD; d++) {
        float wv = w[d * GG];
#pragma unroll
        for (int v = 0; v < 16; v++) acc[v] += wv * sx[v * DD + d];
    }
    float* out = &g_vxg[((key * 16 + b) * 16) * GG + g];
#pragma unroll
    for (int v = 0; v < 16; v++) out[v * GG] = acc[v];
}

// ---------------- K6: visit GRU recurrence -------------------------------------
// grid (16, 7), block 384, dyn smem = (DD*GG + DD + GG)*4 = 198656 B
__global__ void __launch_bounds__(384) k_vis_gru(const float* bhh) {
    extern __shared__ float sm[];
    float* s_w = sm;
    float* s_h = sm + DD * GG;
    float* s_gh = s_h + DD;
    int key = blockIdx.y, b = blockIdx.x, g = threadIdx.x;
    for (int i = g; i < DD * GG; i += GG) s_w[i] = g_wT[WHH_V + key * (DD * GG) + i];
    if (g < DD) s_h[g] = 0.f;
    __syncthreads();
    float bb = bhh[key * GG + g];
    for (int t = 0; t < 16; t++) {
        float acc = bb;
#pragma unroll 4
        for (int d = 0; d < DD; d++) acc += s_w[d * GG + g] * s_h[d];
        s_gh[g] = acc;
        __syncthreads();
        if (g < DD) {
            const float* xg = &g_vxg[((key * 16 + b) * 16 + t) * GG];
            float r = sigf(xg[g] + s_gh[g]);
            float z = sigf(xg[DD + g] + s_gh[DD + g]);
            float nn = tanhf(xg[2 * DD + g] + r * s_gh[2 * DD + g]);
            s_h[g] = (1.f - z) * nn + z * s_h[g];
        }
        __syncthreads();
    }
    if (g < DD) g_hv[(key * 16 + b) * DD + g] = s_h[g];
}

// ---------------- K7: ReLU + final FC --------------------------------------------
__global__ void k_fc(const float* fcw, const float* fcb, float* out) {
    __shared__ float pe[7 * DD];
    int b = blockIdx.x, o = threadIdx.x;
    for (int i = o; i < 7 * DD; i += 256) {
        int k = i / DD, d = i % DD;
        pe[i] = fmaxf(g_hv[(k * 16 + b) * DD + d], 0.f);
    }
    __syncthreads();
    if (o < NOUT) {
        float acc = fcb[o];
        for (int j = 0; j < 7 * DD; j++) acc += pe[j] * fcw[j * NOUT + o];
        out[b * NOUT + o] = acc;
    }
}

// ---------------- launch -----------------------------------------------------------
extern "C" void kernel_launch(void* const* d_in, const int* in_sizes, int n_in,
                              void* d_out, int out_size) {
    const int* tok_cond      = (const int*)d_in[0];
    const int* tok_proc      = (const int*)d_in[1];
    const int* tok_drug      = (const int*)d_in[2];
    const int* tok_lab_item  = (const int*)d_in[3];
    const int* tok_lab_value = (const int*)d_in[4];
    const int* tok_inj_item  = (const int*)d_in[5];
    const int* tok_inj_value = (const int*)d_in[6];
    const float* weight      = (const float*)d_in[7];
    const float* age         = (const float*)d_in[8];
    const float* emb_cond    = (const float*)d_in[9];
    const float* emb_proc    = (const float*)d_in[10];
    const float* emb_drug    = (const float*)d_in[11];
    const float* emb_li      = (const float*)d_in[12];
    const float* emb_lv      = (const float*)d_in[13];
    const float* emb_ii      = (const float*)d_in[14];
    const float* emb_iv      = (const float*)d_in[15];
    const float* mgru_wih    = (const float*)d_in[16];
    const float* mgru_whh    = (const float*)d_in[17];
    const float* mgru_bih    = (const float*)d_in[18];
    const float* mgru_bhh    = (const float*)d_in[19];
    const float* vgru_wih    = (const float*)d_in[20];
    const float* vgru_whh    = (const float*)d_in[21];
    const float* vgru_bih    = (const float*)d_in[22];
    const float* vgru_bhh    = (const float*)d_in[23];
    const float* info_w      = (const float*)d_in[24];
    const float* info_b      = (const float*)d_in[25];
    const float* fc_w        = (const float*)d_in[26];
    const float* fc_b        = (const float*)d_in[27];
    float* out = (float*)d_out;

    cudaFuncSetAttribute(k_mon_gru, cudaFuncAttributeMaxDynamicSharedMemorySize, 221184);
    cudaFuncSetAttribute(k_vis_gru, cudaFuncAttributeMaxDynamicSharedMemorySize, 198656);

    k_transpose<<<dim3(384, 24), 128>>>(mgru_wih, mgru_whh, vgru_wih, vgru_whh);
    k_embed_visit<<<dim3(256, 3), 128>>>(tok_cond, tok_proc, tok_drug,
                                         emb_cond, emb_proc, emb_drug);
    k_embed_mon<<<dim3(2048, 2), 128>>>(tok_lab_item, tok_lab_value,
                                        tok_inj_item, tok_inj_value,
                                        emb_li, emb_lv, emb_ii, emb_iv);
    k_xg34<<<dim3(256, 2), 384>>>(mgru_bih);
    k_xg012<<<dim3(256, 3), 384>>>(mgru_bih);
    k_mon_gru<<<dim3(29, 5), 384, 221184>>>(mgru_whh, mgru_bhh);
    k_vxg<<<dim3(16, 7), 384>>>(weight, age, info_w, info_b, vgru_bih);
    k_vis_gru<<<dim3(16, 7), 384, 198656>>>(vgru_bhh);
    k_fc<<<16, 256>>>(fc_w, fc_b, out);
}

// round 8
// speedup vs baseline: 1.1871x; 1.1837x over previous
#include <cuda_runtime.h>

#define DD 128
#define GG 384
#define BV 256
#define MM 32
#define LL 24
#define NOUT 193
#define NSEQ 9

// ---------------- scratch (static device globals; no allocation) -------------
__device__ float g_e3[3 * BV * DD];            // cond/proc/drug visit embeddings
__device__ float g_mon[2 * BV * MM * DD];      // lab / inj monitor embeddings
__device__ float g_xg34[2 * BV * MM * GG];     // monitor input-gates, keys 3,4
__device__ float g_xg012[3 * BV * GG];         // monitor input-gates, keys 0-2 (t-invariant)
__device__ float g_h5[5 * BV * DD];            // monitor final hidden
__device__ float g_vxg[7 * 16 * 16 * GG];      // visit input-gates
__device__ float g_hv[7 * 16 * DD];            // visit final hidden
__device__ float g_wT[24 * DD * GG];           // transposed weights [d][g]

#define WIH_M 0
#define WHH_M (5 * DD * GG)
#define WIH_V (10 * DD * GG)
#define WHH_V (17 * DD * GG)

__device__ __forceinline__ float sigf(float x) { return 1.0f / (1.0f + __expf(-x)); }

// ---------------- K0: transpose all GRU weights to [d][g] --------------------
__global__ void k_transpose(const float* mih, const float* mhh,
                            const float* vih, const float* vhh) {
    int y = blockIdx.y;      // 0..23: which (tensor,key)
    int g = blockIdx.x;      // 0..383
    int d = threadIdx.x;     // 0..127
    const float* src; int k;
    if (y < 5)       { src = mih; k = y; }
    else if (y < 10) { src = mhh; k = y - 5; }
    else if (y < 17) { src = vih; k = y - 10; }
    else             { src = vhh; k = y - 17; }
    g_wT[y * (DD * GG) + d * GG + g] = src[(k * GG + g) * DD + d];
}

// ---------------- K1: visit-event embedding sums ------------------------------
__global__ void k_embed_visit(const int* tc, const int* tp, const int* td,
                              const float* ec, const float* ep, const float* ed) {
    int n = blockIdx.x, key = blockIdx.y, d = threadIdx.x;
    const int* tok = (key == 0) ? tc : (key == 1) ? tp : td;
    const float* emb = (key == 0) ? ec : (key == 1) ? ep : ed;
    float acc = 0.f;
#pragma unroll
    for (int l = 0; l < LL; l++) acc += emb[tok[n * LL + l] * DD + d];
    g_e3[(key * BV + n) * DD + d] = acc;
}

// ---------------- K2: monitor-event pair embedding sums (float4) -------------
__global__ void k_embed_mon(const int* __restrict__ tli, const int* __restrict__ tlv,
                            const int* __restrict__ tii, const int* __restrict__ tiv,
                            const float* __restrict__ eli, const float* __restrict__ elv,
                            const float* __restrict__ eii, const float* __restrict__ eiv) {
    int pair = blockIdx.y;
    int r = blockIdx.x * 4 + (threadIdx.x >> 5);   // monitor row 0..8191
    int lane = threadIdx.x & 31;
    const int* ti = pair ? tii : tli;
    const int* tv = pair ? tiv : tlv;
    const float4* ei = (const float4*)(pair ? eii : eli);
    const float4* ev = (const float4*)(pair ? eiv : elv);
    float4 acc = make_float4(0.f, 0.f, 0.f, 0.f);
#pragma unroll
    for (int l = 0; l < LL; l++) {
        int a = ti[r * LL + l];
        int b = tv[r * LL + l];
        float4 x = ei[a * 32 + lane];
        float4 y = ev[b * 32 + lane];
        acc.x += x.x * y.x; acc.y += x.y * y.y;
        acc.z += x.z * y.z; acc.w += x.w * y.w;
    }
    ((float4*)g_mon)[(pair * 8192 + r) * 32 + lane] = acc;
}

// ---------------- K3a: monitor input-gates for keys 3,4 (R2 version) ----------
__global__ void __launch_bounds__(384) k_xg34(const float* bih) {
    __shared__ float sx[DD * 36];   // x transposed [d][t], pad 4 (16B-aligned rows)
    int pair = blockIdx.y, n = blockIdx.x, key = 3 + pair;
    int g = threadIdx.x;
    for (int i = g; i < MM * DD; i += GG) {
        int t = i / DD, d = i % DD;
        sx[d * 36 + t] = g_mon[((pair * BV + n) * MM + t) * DD + d];
    }
    __syncthreads();
    float b = bih[key * GG + g];
    float acc[MM];
#pragma unroll
    for (int t = 0; t < MM; t++) acc[t] = b;
    const float* w = &g_wT[WIH_M + key * (DD * GG) + g];
    for (int d = 0; d < DD; d++) {
        float wv = w[d * GG];
        const float4* x4 = (const float4*)&sx[d * 36];
#pragma unroll
        for (int q = 0; q < 8; q++) {
            float4 x = x4[q];
            acc[q * 4 + 0] += wv * x.x; acc[q * 4 + 1] += wv * x.y;
            acc[q * 4 + 2] += wv * x.z; acc[q * 4 + 3] += wv * x.w;
        }
    }
    float* out = &g_xg34[((pair * BV + n) * MM) * GG + g];
#pragma unroll
    for (int t = 0; t < MM; t++) out[t * GG] = acc[t];
}

// ---------------- K3b: monitor input-gates for keys 0-2 (t-invariant) --------
__global__ void k_xg012(const float* bih) {
    __shared__ float sx[DD];
    int key = blockIdx.y, n = blockIdx.x, g = threadIdx.x;
    if (g < DD) sx[g] = g_e3[(key * BV + n) * DD + g];
    __syncthreads();
    float acc = bih[key * GG + g];
    const float* w = &g_wT[WIH_M + key * (DD * GG) + g];
#pragma unroll 4
    for (int d = 0; d < DD; d++) acc += w[d * GG] * sx[d];
    g_xg012[(key * BV + n) * GG + g] = acc;
}

// ---------------- K4: monitor GRU recurrence (scalar FFMA + float4 h + prefetch)
// grid (29, 5), block 384, dyn smem = (DD*GG + NSEQ*DD + NSEQ*GG)*4 = 215040 B
__global__ void __launch_bounds__(384) k_mon_gru(const float* __restrict__ bhh) {
    extern __shared__ float sm[];
    float* s_w = sm;                       // [d][g] 196608 B
    float* s_h = sm + DD * GG;             // [s][128] 4608 B (float4-aligned)
    float* s_gh = s_h + NSEQ * DD;         // [s][384] 13824 B
    int key = blockIdx.y, grp = blockIdx.x, g = threadIdx.x;
    int n0 = grp * NSEQ;
    int ns = min(NSEQ, BV - n0);
    for (int i = g; i < DD * GG; i += GG) s_w[i] = g_wT[WHH_M + key * (DD * GG) + i];
    for (int i = g; i < NSEQ * DD; i += GG) s_h[i] = 0.f;
    __syncthreads();
    float bb = bhh[key * GG + g];
    int ss = g >> 7, dd = g & 127;

    // gate-thread sequence slots: s = ss, ss+3, ss+6
    float xr[3], xz[3], xn[3];
    const float* xgp[3];
    bool val[3];
#pragma unroll
    for (int p = 0; p < 3; p++) {
        int s = ss + p * 3;
        val[p] = (s < ns);
        int n = n0 + s;
        if (key < 3) {
            const float* xg = &g_xg012[(key * BV + (val[p] ? n : n0)) * GG];
            xr[p] = xg[dd]; xz[p] = xg[DD + dd]; xn[p] = xg[2 * DD + dd];
            xgp[p] = nullptr;
        } else {
            xgp[p] = &g_xg34[(((key - 3) * BV + (val[p] ? n : n0)) * MM) * GG];
        }
    }

    for (int t = 0; t < MM; t++) {
        // prefetch this step's xg (keys 3,4) before the dot phase
        if (key >= 3) {
#pragma unroll
            for (int p = 0; p < 3; p++) {
                const float* xg = xgp[p] + t * GG;
                xr[p] = __ldg(xg + dd);
                xz[p] = __ldg(xg + DD + dd);
                xn[p] = __ldg(xg + 2 * DD + dd);
            }
        }
        float acc[NSEQ];
#pragma unroll
        for (int s = 0; s < NSEQ; s++) acc[s] = bb;
#pragma unroll 2
        for (int dc = 0; dc < 32; dc++) {
            const float* wc = &s_w[(4 * dc) * GG + g];
            float w0 = wc[0];
            float w1 = wc[GG];
            float w2 = wc[2 * GG];
            float w3 = wc[3 * GG];
#pragma unroll
            for (int s = 0; s < NSEQ; s++) {
                float4 h = *(const float4*)&s_h[s * DD + 4 * dc];
                acc[s] += w0 * h.x;
                acc[s] += w1 * h.y;
                acc[s] += w2 * h.z;
                acc[s] += w3 * h.w;
            }
        }
#pragma unroll
        for (int s = 0; s < NSEQ; s++) s_gh[s * GG + g] = acc[s];
        __syncthreads();
#pragma unroll
        for (int p = 0; p < 3; p++) {
            int s = ss + p * 3;
            if (val[p]) {
                float ghr = s_gh[s * GG + dd];
                float ghz = s_gh[s * GG + DD + dd];
                float ghn = s_gh[s * GG + 2 * DD + dd];
                float h = s_h[s * DD + dd];
                float r = sigf(xr[p] + ghr);
                float z = sigf(xz[p] + ghz);
                float nn = tanhf(xn[p] + r * ghn);
                s_h[s * DD + dd] = (1.f - z) * nn + z * h;
            }
        }
        __syncthreads();
    }
    for (int i = g; i < ns * DD; i += GG) g_h5[(key * BV + n0) * DD + i] = s_h[i];
}

// ---------------- K5: visit input-gates (R2 version) ---------------------------
__global__ void __launch_bounds__(384) k_vxg(const float* weight, const float* age,
                                             const float* info_w, const float* info_b,
                                             const float* bih) {
    __shared__ float sx[16 * DD];
    int key = blockIdx.y, b = blockIdx.x, g = threadIdx.x;
    for (int i = g; i < 16 * DD; i += GG) {
        int v = i / DD, d = i % DD;
        float x;
        if (key < 5)       x = g_h5[(key * BV + b * 16 + v) * DD + d];
        else if (key == 5) x = weight[b * 16 + v] * info_w[d] + info_b[d];
        else               x = age[b * 16 + v] * info_w[DD + d] + info_b[DD + d];
        sx[i] = x;
    }
    __syncthreads();
    float bb = bih[key * GG + g];
    float acc[16];
#pragma unroll
    for (int v = 0; v < 16; v++) acc[v] = bb;
    const float* w = &g_wT[WIH_V + key * (DD * GG) + g];
    for (int d = 0; d < DD; d++) {
        float wv = w[d * GG];
#pragma unroll
        for (int v = 0; v < 16; v++) acc[v] += wv * sx[v * DD + d];
    }
    float* out = &g_vxg[((key * 16 + b) * 16) * GG + g];
#pragma unroll
    for (int v = 0; v < 16; v++) out[v * GG] = acc[v];
}

// ---------------- K6: visit GRU recurrence -------------------------------------
// grid (16, 7), block 384, dyn smem = (DD*GG + DD + GG)*4 = 198656 B
__global__ void __launch_bounds__(384) k_vis_gru(const float* bhh) {
    extern __shared__ float sm[];
    float* s_w = sm;
    float* s_h = sm + DD * GG;
    float* s_gh = s_h + DD;
    int key = blockIdx.y, b = blockIdx.x, g = threadIdx.x;
    for (int i = g; i < DD * GG; i += GG) s_w[i] = g_wT[WHH_V + key * (DD * GG) + i];
    if (g < DD) s_h[g] = 0.f;
    __syncthreads();
    float bb = bhh[key * GG + g];
    for (int t = 0; t < 16; t++) {
        float acc = bb;
#pragma unroll 4
        for (int d = 0; d < DD; d++) acc += s_w[d * GG + g] * s_h[d];
        s_gh[g] = acc;
        __syncthreads();
        if (g < DD) {
            const float* xg = &g_vxg[((key * 16 + b) * 16 + t) * GG];
            float r = sigf(xg[g] + s_gh[g]);
            float z = sigf(xg[DD + g] + s_gh[DD + g]);
            float nn = tanhf(xg[2 * DD + g] + r * s_gh[2 * DD + g]);
            s_h[g] = (1.f - z) * nn + z * s_h[g];
        }
        __syncthreads();
    }
    if (g < DD) g_hv[(key * 16 + b) * DD + g] = s_h[g];
}

// ---------------- K7: ReLU + final FC --------------------------------------------
__global__ void k_fc(const float* fcw, const float* fcb, float* out) {
    __shared__ float pe[7 * DD];
    int b = blockIdx.x, o = threadIdx.x;
    for (int i = o; i < 7 * DD; i += 256) {
        int k = i / DD, d = i % DD;
        pe[i] = fmaxf(g_hv[(k * 16 + b) * DD + d], 0.f);
    }
    __syncthreads();
    if (o < NOUT) {
        float acc = fcb[o];
        for (int j = 0; j < 7 * DD; j++) acc += pe[j] * fcw[j * NOUT + o];
        out[b * NOUT + o] = acc;
    }
}

// ---------------- launch -----------------------------------------------------------
extern "C" void kernel_launch(void* const* d_in, const int* in_sizes, int n_in,
                              void* d_out, int out_size) {
    const int* tok_cond      = (const int*)d_in[0];
    const int* tok_proc      = (const int*)d_in[1];
    const int* tok_drug      = (const int*)d_in[2];
    const int* tok_lab_item  = (const int*)d_in[3];
    const int* tok_lab_value = (const int*)d_in[4];
    const int* tok_inj_item  = (const int*)d_in[5];
    const int* tok_inj_value = (const int*)d_in[6];
    const float* weight      = (const float*)d_in[7];
    const float* age         = (const float*)d_in[8];
    const float* emb_cond    = (const float*)d_in[9];
    const float* emb_proc    = (const float*)d_in[10];
    const float* emb_drug    = (const float*)d_in[11];
    const float* emb_li      = (const float*)d_in[12];
    const float* emb_lv      = (const float*)d_in[13];
    const float* emb_ii      = (const float*)d_in[14];
    const float* emb_iv      = (const float*)d_in[15];
    const float* mgru_wih    = (const float*)d_in[16];
    const float* mgru_whh    = (const float*)d_in[17];
    const float* mgru_bih    = (const float*)d_in[18];
    const float* mgru_bhh    = (const float*)d_in[19];
    const float* vgru_wih    = (const float*)d_in[20];
    const float* vgru_whh    = (const float*)d_in[21];
    const float* vgru_bih    = (const float*)d_in[22];
    const float* vgru_bhh    = (const float*)d_in[23];
    const float* info_w      = (const float*)d_in[24];
    const float* info_b      = (const float*)d_in[25];
    const float* fc_w        = (const float*)d_in[26];
    const float* fc_b        = (const float*)d_in[27];
    float* out = (float*)d_out;

    cudaFuncSetAttribute(k_mon_gru, cudaFuncAttributeMaxDynamicSharedMemorySize, 215040);
    cudaFuncSetAttribute(k_vis_gru, cudaFuncAttributeMaxDynamicSharedMemorySize, 198656);

    k_transpose<<<dim3(384, 24), 128>>>(mgru_wih, mgru_whh, vgru_wih, vgru_whh);
    k_embed_visit<<<dim3(256, 3), 128>>>(tok_cond, tok_proc, tok_drug,
                                         emb_cond, emb_proc, emb_drug);
    k_embed_mon<<<dim3(2048, 2), 128>>>(tok_lab_item, tok_lab_value,
                                        tok_inj_item, tok_inj_value,
                                        emb_li, emb_lv, emb_ii, emb_iv);
    k_xg34<<<dim3(256, 2), 384>>>(mgru_bih);
    k_xg012<<<dim3(256, 3), 384>>>(mgru_bih);
    k_mon_gru<<<dim3(29, 5), 384, 215040>>>(mgru_bhh);
    k_vxg<<<dim3(16, 7), 384>>>(weight, age, info_w, info_b, vgru_bih);
    k_vis_gru<<<dim3(16, 7), 384, 198656>>>(vgru_bhh);
    k_fc<<<16, 256>>>(fc_w, fc_b, out);
}

// round 9
// speedup vs baseline: 1.3120x; 1.1052x over previous
#include <cuda_runtime.h>
#include <cstdint>

#define DD 128
#define GG 384
#define BV 256
#define MM 32
#define LL 24
#define NOUT 193
#define NSEQ 9

// ---------------- scratch (static device globals; no allocation) -------------
__device__ float g_e3[3 * BV * DD];            // cond/proc/drug visit embeddings
__device__ float g_mon[2 * BV * MM * DD];      // lab / inj monitor embeddings
__device__ float g_xg34[2 * BV * MM * GG];     // monitor input-gates, keys 3,4
__device__ float g_xg012[3 * BV * GG];         // monitor input-gates, keys 0-2 (t-invariant)
__device__ float g_h5[5 * BV * DD];            // monitor final hidden
__device__ float g_vxg[7 * 16 * 16 * GG];      // visit input-gates
__device__ float g_hv[7 * 16 * DD];            // visit final hidden
__device__ float g_wT[24 * DD * GG];           // transposed weights [d][g]
__device__ uint2 g_wB34[2 * 48 * 16 * 32];     // tf32 B fragments for keys 3,4

#define WIH_M 0
#define WHH_M (5 * DD * GG)
#define WIH_V (10 * DD * GG)
#define WHH_V (17 * DD * GG)

__device__ __forceinline__ float sigf(float x) { return 1.0f / (1.0f + __expf(-x)); }

__device__ __forceinline__ uint32_t f2tf32(float x) {
    uint32_t u; asm("cvt.rna.tf32.f32 %0, %1;" : "=r"(u) : "f"(x)); return u;
}
__device__ __forceinline__ void mma_tf32(float* c, const uint32_t* a, uint2 b) {
    asm volatile("mma.sync.aligned.m16n8k8.row.col.f32.tf32.tf32.f32 "
                 "{%0,%1,%2,%3}, {%4,%5,%6,%7}, {%8,%9}, {%0,%1,%2,%3};"
                 : "+f"(c[0]), "+f"(c[1]), "+f"(c[2]), "+f"(c[3])
                 : "r"(a[0]), "r"(a[1]), "r"(a[2]), "r"(a[3]), "r"(b.x), "r"(b.y));
}

// ---------------- K0: transpose all GRU weights to [d][g] --------------------
__global__ void k_transpose(const float* mih, const float* mhh,
                            const float* vih, const float* vhh) {
    int y = blockIdx.y;      // 0..23: which (tensor,key)
    int g = blockIdx.x;      // 0..383
    int d = threadIdx.x;     // 0..127
    const float* src; int k;
    if (y < 5)       { src = mih; k = y; }
    else if (y < 10) { src = mhh; k = y - 5; }
    else if (y < 17) { src = vih; k = y - 10; }
    else             { src = vhh; k = y - 17; }
    g_wT[y * (DD * GG) + d * GG + g] = src[(k * GG + g) * DD + d];
}

// ---------------- K0b: pack W keys 3,4 into tf32 B fragments -------------------
__global__ void k_packB34(const float* __restrict__ wih) {
    int idx = blockIdx.x * 256 + threadIdx.x;   // < 49152
    int lane = idx & 31;
    int ks = (idx >> 5) & 15;
    int tmp = idx >> 9;
    int pair = tmp / 48, nt = tmp % 48;
    int n = nt * 8 + (lane >> 2);
    int k = ks * 8 + (lane & 3);
    const float* W = wih + (3 + pair) * (GG * DD);
    uint2 o;
    o.x = f2tf32(W[n * DD + k]);
    o.y = f2tf32(W[n * DD + k + 4]);
    g_wB34[idx] = o;
}

// ---------------- K1: visit-event embedding sums ------------------------------
__global__ void k_embed_visit(const int* tc, const int* tp, const int* td,
                              const float* ec, const float* ep, const float* ed) {
    int n = blockIdx.x, key = blockIdx.y, d = threadIdx.x;
    const int* tok = (key == 0) ? tc : (key == 1) ? tp : td;
    const float* emb = (key == 0) ? ec : (key == 1) ? ep : ed;
    float acc = 0.f;
#pragma unroll
    for (int l = 0; l < LL; l++) acc += emb[tok[n * LL + l] * DD + d];
    g_e3[(key * BV + n) * DD + d] = acc;
}

// ---------------- K2: monitor-event pair embedding sums (float4) -------------
__global__ void k_embed_mon(const int* __restrict__ tli, const int* __restrict__ tlv,
                            const int* __restrict__ tii, const int* __restrict__ tiv,
                            const float* __restrict__ eli, const float* __restrict__ elv,
                            const float* __restrict__ eii, const float* __restrict__ eiv) {
    int pair = blockIdx.y;
    int r = blockIdx.x * 4 + (threadIdx.x >> 5);   // monitor row 0..8191
    int lane = threadIdx.x & 31;
    const int* ti = pair ? tii : tli;
    const int* tv = pair ? tiv : tlv;
    const float4* ei = (const float4*)(pair ? eii : eli);
    const float4* ev = (const float4*)(pair ? eiv : elv);
    float4 acc = make_float4(0.f, 0.f, 0.f, 0.f);
#pragma unroll
    for (int l = 0; l < LL; l++) {
        int a = ti[r * LL + l];
        int b = tv[r * LL + l];
        float4 x = ei[a * 32 + lane];
        float4 y = ev[b * 32 + lane];
        acc.x += x.x * y.x; acc.y += x.y * y.y;
        acc.z += x.z * y.z; acc.w += x.w * y.w;
    }
    ((float4*)g_mon)[(pair * 8192 + r) * 32 + lane] = acc;
}

// ---------------- K3a: monitor input-gates keys 3,4 — tf32 mma.sync -----------
// grid (256, 2), block 256 (8 warps). Each warp: m=32 (2 tiles) x n=48 (6 tiles).
__global__ void __launch_bounds__(256) k_xg34_mma(const float* __restrict__ bih) {
    __shared__ float sX[32 * 132];
    int pair = blockIdx.y, n = blockIdx.x, key = 3 + pair;
    int tid = threadIdx.x, lane = tid & 31, wid = tid >> 5;
    const float* xsrc = &g_mon[(pair * BV + n) * MM * DD];
    for (int i = tid; i < 32 * 128; i += 256)
        sX[(i >> 7) * 132 + (i & 127)] = xsrc[i];
    __syncthreads();
    int r = lane >> 2, cc = lane & 3;
    float c[2][6][4];
#pragma unroll
    for (int m = 0; m < 2; m++)
#pragma unroll
        for (int j = 0; j < 6; j++)
#pragma unroll
            for (int q = 0; q < 4; q++) c[m][j][q] = 0.f;
    const uint2* Bbase = &g_wB34[((pair * 48 + wid * 6) * 16) * 32 + lane];
#pragma unroll 4
    for (int ks = 0; ks < 16; ks++) {
        int k0 = ks * 8;
        uint32_t A[2][4];
#pragma unroll
        for (int m = 0; m < 2; m++) {
            int row = m * 16 + r;
            A[m][0] = f2tf32(sX[row * 132 + k0 + cc]);
            A[m][1] = f2tf32(sX[(row + 8) * 132 + k0 + cc]);
            A[m][2] = f2tf32(sX[row * 132 + k0 + cc + 4]);
            A[m][3] = f2tf32(sX[(row + 8) * 132 + k0 + cc + 4]);
        }
#pragma unroll
        for (int j = 0; j < 6; j++) {
            uint2 b = Bbase[(j * 16 + ks) * 32];
            mma_tf32(c[0][j], A[0], b);
            mma_tf32(c[1][j], A[1], b);
        }
    }
    float* outbase = &g_xg34[((pair * BV + n) * MM) * GG];
#pragma unroll
    for (int j = 0; j < 6; j++) {
        int col = wid * 48 + j * 8 + 2 * cc;
        float2 bias = *(const float2*)&bih[key * GG + col];
#pragma unroll
        for (int m = 0; m < 2; m++) {
            int row0 = m * 16 + r;
            float2 v0 = make_float2(c[m][j][0] + bias.x, c[m][j][1] + bias.y);
            float2 v1 = make_float2(c[m][j][2] + bias.x, c[m][j][3] + bias.y);
            *(float2*)&outbase[row0 * GG + col] = v0;
            *(float2*)&outbase[(row0 + 8) * GG + col] = v1;
        }
    }
}

// ---------------- K3b: monitor input-gates for keys 0-2 (t-invariant) --------
__global__ void k_xg012(const float* bih) {
    __shared__ float sx[DD];
    int key = blockIdx.y, n = blockIdx.x, g = threadIdx.x;
    if (g < DD) sx[g] = g_e3[(key * BV + n) * DD + g];
    __syncthreads();
    float acc = bih[key * GG + g];
    const float* w = &g_wT[WIH_M + key * (DD * GG) + g];
#pragma unroll 4
    for (int d = 0; d < DD; d++) acc += w[d * GG] * sx[d];
    g_xg012[(key * BV + n) * GG + g] = acc;
}

// ---------------- K4: monitor GRU recurrence (scalar FFMA + float4 h + prefetch)
// grid (29, 5), block 384, dyn smem = (DD*GG + NSEQ*DD + NSEQ*GG)*4 = 215040 B
__global__ void __launch_bounds__(384) k_mon_gru(const float* __restrict__ bhh) {
    extern __shared__ float sm[];
    float* s_w = sm;                       // [d][g] 196608 B
    float* s_h = sm + DD * GG;             // [s][128] 4608 B (float4-aligned)
    float* s_gh = s_h + NSEQ * DD;         // [s][384] 13824 B
    int key = blockIdx.y, grp = blockIdx.x, g = threadIdx.x;
    int n0 = grp * NSEQ;
    int ns = min(NSEQ, BV - n0);
    for (int i = g; i < DD * GG; i += GG) s_w[i] = g_wT[WHH_M + key * (DD * GG) + i];
    for (int i = g; i < NSEQ * DD; i += GG) s_h[i] = 0.f;
    __syncthreads();
    float bb = bhh[key * GG + g];
    int ss = g >> 7, dd = g & 127;

    // gate-thread sequence slots: s = ss, ss+3, ss+6
    float xr[3], xz[3], xn[3];
    const float* xgp[3];
    bool val[3];
#pragma unroll
    for (int p = 0; p < 3; p++) {
        int s = ss + p * 3;
        val[p] = (s < ns);
        int n = n0 + s;
        if (key < 3) {
            const float* xg = &g_xg012[(key * BV + (val[p] ? n : n0)) * GG];
            xr[p] = xg[dd]; xz[p] = xg[DD + dd]; xn[p] = xg[2 * DD + dd];
            xgp[p] = nullptr;
        } else {
            xgp[p] = &g_xg34[(((key - 3) * BV + (val[p] ? n : n0)) * MM) * GG];
        }
    }

    for (int t = 0; t < MM; t++) {
        // prefetch this step's xg (keys 3,4) before the dot phase
        if (key >= 3) {
#pragma unroll
            for (int p = 0; p < 3; p++) {
                const float* xg = xgp[p] + t * GG;
                xr[p] = __ldg(xg + dd);
                xz[p] = __ldg(xg + DD + dd);
                xn[p] = __ldg(xg + 2 * DD + dd);
            }
        }
        float acc[NSEQ];
#pragma unroll
        for (int s = 0; s < NSEQ; s++) acc[s] = bb;
#pragma unroll 2
        for (int dc = 0; dc < 32; dc++) {
            const float* wc = &s_w[(4 * dc) * GG + g];
            float w0 = wc[0];
            float w1 = wc[GG];
            float w2 = wc[2 * GG];
            float w3 = wc[3 * GG];
#pragma unroll
            for (int s = 0; s < NSEQ; s++) {
                float4 h = *(const float4*)&s_h[s * DD + 4 * dc];
                acc[s] += w0 * h.x;
                acc[s] += w1 * h.y;
                acc[s] += w2 * h.z;
                acc[s] += w3 * h.w;
            }
        }
#pragma unroll
        for (int s = 0; s < NSEQ; s++) s_gh[s * GG + g] = acc[s];
        __syncthreads();
#pragma unroll
        for (int p = 0; p < 3; p++) {
            int s = ss + p * 3;
            if (val[p]) {
                float ghr = s_gh[s * GG + dd];
                float ghz = s_gh[s * GG + DD + dd];
                float ghn = s_gh[s * GG + 2 * DD + dd];
                float h = s_h[s * DD + dd];
                float r = sigf(xr[p] + ghr);
                float z = sigf(xz[p] + ghz);
                float nn = tanhf(xn[p] + r * ghn);
                s_h[s * DD + dd] = (1.f - z) * nn + z * h;
            }
        }
        __syncthreads();
    }
    for (int i = g; i < ns * DD; i += GG) g_h5[(key * BV + n0) * DD + i] = s_h[i];
}

// ---------------- K5: visit input-gates (R2 version) ---------------------------
__global__ void __launch_bounds__(384) k_vxg(const float* weight, const float* age,
                                             const float* info_w, const float* info_b,
                                             const float* bih) {
    __shared__ float sx[16 * DD];
    int key = blockIdx.y, b = blockIdx.x, g = threadIdx.x;
    for (int i = g; i < 16 * DD; i += GG) {
        int v = i / DD, d = i % DD;
        float x;
        if (key < 5)       x = g_h5[(key * BV + b * 16 + v) * DD + d];
        else if (key == 5) x = weight[b * 16 + v] * info_w[d] + info_b[d];
        else               x = age[b * 16 + v] * info_w[DD + d] + info_b[DD + d];
        sx[i] = x;
    }
    __syncthreads();
    float bb = bih[key * GG + g];
    float acc[16];
#pragma unroll
    for (int v = 0; v < 16; v++) acc[v] = bb;
    const float* w = &g_wT[WIH_V + key * (DD * GG) + g];
    for (int d = 0; d < DD; d++) {
        float wv = w[d * GG];
#pragma unroll
        for (int v = 0; v < 16; v++) acc[v] += wv * sx[v * DD + d];
    }
    float* out = &g_vxg[((key * 16 + b) * 16) * GG + g];
#pragma unroll
    for (int v = 0; v < 16; v++) out[v * GG] = acc[v];
}

// ---------------- K6: visit GRU recurrence -------------------------------------
// grid (16, 7), block 384, dyn smem = (DD*GG + DD + GG)*4 = 198656 B
__global__ void __launch_bounds__(384) k_vis_gru(const float* bhh) {
    extern __shared__ float sm[];
    float* s_w = sm;
    float* s_h = sm + DD * GG;
    float* s_gh = s_h + DD;
    int key = blockIdx.y, b = blockIdx.x, g = threadIdx.x;
    for (int i = g; i < DD * GG; i += GG) s_w[i] = g_wT[WHH_V + key * (DD * GG) + i];
    if (g < DD) s_h[g] = 0.f;
    __syncthreads();
    float bb = bhh[key * GG + g];
    for (int t = 0; t < 16; t++) {
        float acc = bb;
#pragma unroll 4
        for (int d = 0; d < DD; d++) acc += s_w[d * GG + g] * s_h[d];
        s_gh[g] = acc;
        __syncthreads();
        if (g < DD) {
            const float* xg = &g_vxg[((key * 16 + b) * 16 + t) * GG];
            float r = sigf(xg[g] + s_gh[g]);
            float z = sigf(xg[DD + g] + s_gh[DD + g]);
            float nn = tanhf(xg[2 * DD + g] + r * s_gh[2 * DD + g]);
            s_h[g] = (1.f - z) * nn + z * s_h[g];
        }
        __syncthreads();
    }
    if (g < DD) g_hv[(key * 16 + b) * DD + g] = s_h[g];
}

// ---------------- K7: ReLU + final FC --------------------------------------------
__global__ void k_fc(const float* fcw, const float* fcb, float* out) {
    __shared__ float pe[7 * DD];
    int b = blockIdx.x, o = threadIdx.x;
    for (int i = o; i < 7 * DD; i += 256) {
        int k = i / DD, d = i % DD;
        pe[i] = fmaxf(g_hv[(k * 16 + b) * DD + d], 0.f);
    }
    __syncthreads();
    if (o < NOUT) {
        float acc = fcb[o];
        for (int j = 0; j < 7 * DD; j++) acc += pe[j] * fcw[j * NOUT + o];
        out[b * NOUT + o] = acc;
    }
}

// ---------------- launch -----------------------------------------------------------
extern "C" void kernel_launch(void* const* d_in, const int* in_sizes, int n_in,
                              void* d_out, int out_size) {
    const int* tok_cond      = (const int*)d_in[0];
    const int* tok_proc      = (const int*)d_in[1];
    const int* tok_drug      = (const int*)d_in[2];
    const int* tok_lab_item  = (const int*)d_in[3];
    const int* tok_lab_value = (const int*)d_in[4];
    const int* tok_inj_item  = (const int*)d_in[5];
    const int* tok_inj_value = (const int*)d_in[6];
    const float* weight      = (const float*)d_in[7];
    const float* age         = (const float*)d_in[8];
    const float* emb_cond    = (const float*)d_in[9];
    const float* emb_proc    = (const float*)d_in[10];
    const float* emb_drug    = (const float*)d_in[11];
    const float* emb_li      = (const float*)d_in[12];
    const float* emb_lv      = (const float*)d_in[13];
    const float* emb_ii      = (const float*)d_in[14];
    const float* emb_iv      = (const float*)d_in[15];
    const float* mgru_wih    = (const float*)d_in[16];
    const float* mgru_whh    = (const float*)d_in[17];
    const float* mgru_bih    = (const float*)d_in[18];
    const float* mgru_bhh    = (const float*)d_in[19];
    const float* vgru_wih    = (const float*)d_in[20];
    const float* vgru_whh    = (const float*)d_in[21];
    const float* vgru_bih    = (const float*)d_in[22];
    const float* vgru_bhh    = (const float*)d_in[23];
    const float* info_w      = (const float*)d_in[24];
    const float* info_b      = (const float*)d_in[25];
    const float* fc_w        = (const float*)d_in[26];
    const float* fc_b        = (const float*)d_in[27];
    float* out = (float*)d_out;

    cudaFuncSetAttribute(k_mon_gru, cudaFuncAttributeMaxDynamicSharedMemorySize, 215040);
    cudaFuncSetAttribute(k_vis_gru, cudaFuncAttributeMaxDynamicSharedMemorySize, 198656);

    k_transpose<<<dim3(384, 24), 128>>>(mgru_wih, mgru_whh, vgru_wih, vgru_whh);
    k_packB34<<<192, 256>>>(mgru_wih);
    k_embed_visit<<<dim3(256, 3), 128>>>(tok_cond, tok_proc, tok_drug,
                                         emb_cond, emb_proc, emb_drug);
    k_embed_mon<<<dim3(2048, 2), 128>>>(tok_lab_item, tok_lab_value,
                                        tok_inj_item, tok_inj_value,
                                        emb_li, emb_lv, emb_ii, emb_iv);
    k_xg34_mma<<<dim3(256, 2), 256>>>(mgru_bih);
    k_xg012<<<dim3(256, 3), 384>>>(mgru_bih);
    k_mon_gru<<<dim3(29, 5), 384, 215040>>>(mgru_bhh);
    k_vxg<<<dim3(16, 7), 384>>>(weight, age, info_w, info_b, vgru_bih);
    k_vis_gru<<<dim3(16, 7), 384, 198656>>>(vgru_bhh);
    k_fc<<<16, 256>>>(fc_w, fc_b, out);
}

// round 10
// speedup vs baseline: 1.7258x; 1.3154x over previous
#include <cuda_runtime.h>
#include <cstdint>

#define DD 128
#define GG 384
#define BV 256
#define MM 32
#define LL 24
#define NOUT 193

// ---------------- scratch (static device globals; no allocation) -------------
__device__ float g_e3[3 * BV * DD];            // cond/proc/drug visit embeddings
__device__ float g_mon[2 * BV * MM * DD];      // lab / inj monitor embeddings
__device__ float g_xg34[2 * BV * MM * GG];     // monitor input-gates, keys 3,4
__device__ float g_xg012[3 * BV * GG];         // monitor input-gates, keys 0-2 (t-invariant)
__device__ float g_h5[5 * BV * DD];            // monitor final hidden
__device__ float g_vxg[7 * 16 * 16 * GG];      // visit input-gates
__device__ float g_hv[7 * 16 * DD];            // visit final hidden
__device__ float g_wT[24 * DD * GG];           // transposed weights [d][g] (17 slices used)
__device__ uint2 g_wB34[2 * 48 * 16 * 32];     // tf32 B fragments: mgru_wih keys 3,4
__device__ uint2 g_wBhh[5 * 48 * 16 * 32];     // tf32 B fragments: mgru_whh keys 0..4

#define WIH_M 0
#define WIH_V (10 * DD * GG)
#define WHH_V (17 * DD * GG)

__device__ __forceinline__ float sigf(float x) { return 1.0f / (1.0f + __expf(-x)); }

__device__ __forceinline__ uint32_t f2tf32(float x) {
    uint32_t u; asm("cvt.rna.tf32.f32 %0, %1;" : "=r"(u) : "f"(x)); return u;
}
__device__ __forceinline__ void mma_tf32(float* c, const uint32_t* a, uint2 b) {
    asm volatile("mma.sync.aligned.m16n8k8.row.col.f32.tf32.tf32.f32 "
                 "{%0,%1,%2,%3}, {%4,%5,%6,%7}, {%8,%9}, {%0,%1,%2,%3};"
                 : "+f"(c[0]), "+f"(c[1]), "+f"(c[2]), "+f"(c[3])
                 : "r"(a[0]), "r"(a[1]), "r"(a[2]), "r"(a[3]), "r"(b.x), "r"(b.y));
}

// ---------------- K0: transpose needed GRU weights to [d][g] ------------------
__global__ void k_transpose(const float* mih, const float* vih, const float* vhh) {
    int y = blockIdx.y;      // 0..16
    int g = blockIdx.x;      // 0..383
    int d = threadIdx.x;     // 0..127
    const float* src; int k, slice;
    if (y < 3)       { src = mih; k = y;      slice = y; }            // WIH_M keys 0-2
    else if (y < 10) { src = vih; k = y - 3;  slice = 10 + (y - 3); } // WIH_V
    else             { src = vhh; k = y - 10; slice = 17 + (y - 10);} // WHH_V
    g_wT[slice * (DD * GG) + d * GG + g] = src[(k * GG + g) * DD + d];
}

// ---------------- K0b: pack mgru_wih keys 3,4 into tf32 B fragments -----------
__global__ void k_packB34(const float* __restrict__ wih) {
    int idx = blockIdx.x * 256 + threadIdx.x;   // < 49152
    int lane = idx & 31;
    int ks = (idx >> 5) & 15;
    int tmp = idx >> 9;
    int pair = tmp / 48, nt = tmp % 48;
    int n = nt * 8 + (lane >> 2);
    int k = ks * 8 + (lane & 3);
    const float* W = wih + (3 + pair) * (GG * DD);
    uint2 o;
    o.x = f2tf32(W[n * DD + k]);
    o.y = f2tf32(W[n * DD + k + 4]);
    g_wB34[idx] = o;
}

// ---------------- K0c: pack mgru_whh (5 keys) into tf32 B fragments -----------
__global__ void k_packBhh(const float* __restrict__ whh) {
    int idx = blockIdx.x * 256 + threadIdx.x;   // < 122880
    int lane = idx & 31;
    int ks = (idx >> 5) & 15;
    int tmp = idx >> 9;
    int key = tmp / 48, nt = tmp % 48;
    int n = nt * 8 + (lane >> 2);
    int k = ks * 8 + (lane & 3);
    const float* W = whh + key * (GG * DD);
    uint2 o;
    o.x = f2tf32(W[n * DD + k]);
    o.y = f2tf32(W[n * DD + k + 4]);
    g_wBhh[idx] = o;
}

// ---------------- K1: visit-event embedding sums ------------------------------
__global__ void k_embed_visit(const int* tc, const int* tp, const int* td,
                              const float* ec, const float* ep, const float* ed) {
    int n = blockIdx.x, key = blockIdx.y, d = threadIdx.x;
    const int* tok = (key == 0) ? tc : (key == 1) ? tp : td;
    const float* emb = (key == 0) ? ec : (key == 1) ? ep : ed;
    float acc = 0.f;
#pragma unroll
    for (int l = 0; l < LL; l++) acc += emb[tok[n * LL + l] * DD + d];
    g_e3[(key * BV + n) * DD + d] = acc;
}

// ---------------- K2: monitor-event pair embedding sums (float4) -------------
__global__ void k_embed_mon(const int* __restrict__ tli, const int* __restrict__ tlv,
                            const int* __restrict__ tii, const int* __restrict__ tiv,
                            const float* __restrict__ eli, const float* __restrict__ elv,
                            const float* __restrict__ eii, const float* __restrict__ eiv) {
    int pair = blockIdx.y;
    int r = blockIdx.x * 4 + (threadIdx.x >> 5);   // monitor row 0..8191
    int lane = threadIdx.x & 31;
    const int* ti = pair ? tii : tli;
    const int* tv = pair ? tiv : tlv;
    const float4* ei = (const float4*)(pair ? eii : eli);
    const float4* ev = (const float4*)(pair ? eiv : elv);
    float4 acc = make_float4(0.f, 0.f, 0.f, 0.f);
#pragma unroll
    for (int l = 0; l < LL; l++) {
        int a = ti[r * LL + l];
        int b = tv[r * LL + l];
        float4 x = ei[a * 32 + lane];
        float4 y = ev[b * 32 + lane];
        acc.x += x.x * y.x; acc.y += x.y * y.y;
        acc.z += x.z * y.z; acc.w += x.w * y.w;
    }
    ((float4*)g_mon)[(pair * 8192 + r) * 32 + lane] = acc;
}

// ---------------- K3a: monitor input-gates keys 3,4 — tf32 mma.sync -----------
__global__ void __launch_bounds__(256) k_xg34_mma(const float* __restrict__ bih) {
    __shared__ float sX[32 * 132];
    int pair = blockIdx.y, n = blockIdx.x, key = 3 + pair;
    int tid = threadIdx.x, lane = tid & 31, wid = tid >> 5;
    const float* xsrc = &g_mon[(pair * BV + n) * MM * DD];
    for (int i = tid; i < 32 * 128; i += 256)
        sX[(i >> 7) * 132 + (i & 127)] = xsrc[i];
    __syncthreads();
    int r = lane >> 2, cc = lane & 3;
    float c[2][6][4];
#pragma unroll
    for (int m = 0; m < 2; m++)
#pragma unroll
        for (int j = 0; j < 6; j++)
#pragma unroll
            for (int q = 0; q < 4; q++) c[m][j][q] = 0.f;
    const uint2* Bbase = &g_wB34[((pair * 48 + wid * 6) * 16) * 32 + lane];
#pragma unroll 4
    for (int ks = 0; ks < 16; ks++) {
        int k0 = ks * 8;
        uint32_t A[2][4];
#pragma unroll
        for (int m = 0; m < 2; m++) {
            int row = m * 16 + r;
            A[m][0] = f2tf32(sX[row * 132 + k0 + cc]);
            A[m][1] = f2tf32(sX[(row + 8) * 132 + k0 + cc]);
            A[m][2] = f2tf32(sX[row * 132 + k0 + cc + 4]);
            A[m][3] = f2tf32(sX[(row + 8) * 132 + k0 + cc + 4]);
        }
#pragma unroll
        for (int j = 0; j < 6; j++) {
            uint2 b = Bbase[(j * 16 + ks) * 32];
            mma_tf32(c[0][j], A[0], b);
            mma_tf32(c[1][j], A[1], b);
        }
    }
    float* outbase = &g_xg34[((pair * BV + n) * MM) * GG];
#pragma unroll
    for (int j = 0; j < 6; j++) {
        int col = wid * 48 + j * 8 + 2 * cc;
        float2 bias = *(const float2*)&bih[key * GG + col];
#pragma unroll
        for (int m = 0; m < 2; m++) {
            int row0 = m * 16 + r;
            float2 v0 = make_float2(c[m][j][0] + bias.x, c[m][j][1] + bias.y);
            float2 v1 = make_float2(c[m][j][2] + bias.x, c[m][j][3] + bias.y);
            *(float2*)&outbase[row0 * GG + col] = v0;
            *(float2*)&outbase[(row0 + 8) * GG + col] = v1;
        }
    }
}

// ---------------- K3b: monitor input-gates for keys 0-2 (t-invariant) --------
__global__ void k_xg012(const float* bih) {
    __shared__ float sx[DD];
    int key = blockIdx.y, n = blockIdx.x, g = threadIdx.x;
    if (g < DD) sx[g] = g_e3[(key * BV + n) * DD + g];
    __syncthreads();
    float acc = bih[key * GG + g];
    const float* w = &g_wT[WIH_M + key * (DD * GG) + g];
#pragma unroll 4
    for (int d = 0; d < DD; d++) acc += w[d * GG] * sx[d];
    g_xg012[(key * BV + n) * GG + g] = acc;
}

// ---------------- K4: monitor GRU recurrence — tf32 mma dot phase -------------
// grid (16, 5), block 256 (8 warps), dyn smem = 230144 B
//   s_wB : 24576 uint2 (196608 B)   Whh tf32 fragments for this key
//   s_h  : [16][132] fp32           hidden state
//   s_gh : [16][392] fp32           gh staging
__global__ void __launch_bounds__(256) k_mon_gru(const float* __restrict__ bhh) {
    extern __shared__ float sm[];
    uint2* s_wB = (uint2*)sm;                 // 196608 B
    float* s_h  = sm + 49152;                 // 16*132 floats
    float* s_gh = sm + 49152 + 16 * 132;      // 16*392 floats
    int key = blockIdx.y, grp = blockIdx.x;
    int tid = threadIdx.x, lane = tid & 31, wid = tid >> 5;
    int n0 = grp * 16;
    {
        const float4* src = (const float4*)(g_wBhh + key * 24576);
        float4* dst = (float4*)s_wB;
        for (int i = tid; i < 12288; i += 256) dst[i] = src[i];
    }
    for (int i = tid; i < 16 * 132; i += 256) s_h[i] = 0.f;
    __syncthreads();

    // gate-phase mapping: this thread owns (s = sblk*8+p, d = dd)
    int sblk = tid >> 7, dd = tid & 127;
    float br = bhh[key * GG + dd];
    float bz = bhh[key * GG + DD + dd];
    float bn = bhh[key * GG + 2 * DD + dd];
    float xr[8], xz[8], xn[8];
    const float* xgp[8];
#pragma unroll
    for (int p = 0; p < 8; p++) {
        int n = n0 + sblk * 8 + p;
        if (key < 3) {
            const float* xg = &g_xg012[(key * BV + n) * GG];
            xr[p] = xg[dd]; xz[p] = xg[DD + dd]; xn[p] = xg[2 * DD + dd];
            xgp[p] = nullptr;
        } else {
            xgp[p] = &g_xg34[(((key - 3) * BV + n) * MM) * GG];
        }
    }

    int r = lane >> 2, cc = lane & 3;
    const uint2* Bb = s_wB + (wid * 6 * 16) * 32 + lane;

    for (int t = 0; t < MM; t++) {
        if (key >= 3) {
#pragma unroll
            for (int p = 0; p < 8; p++) {
                const float* xg = xgp[p] + t * GG;
                xr[p] = __ldg(xg + dd);
                xz[p] = __ldg(xg + DD + dd);
                xn[p] = __ldg(xg + 2 * DD + dd);
            }
        }
        float c[6][4];
#pragma unroll
        for (int j = 0; j < 6; j++)
#pragma unroll
            for (int q = 0; q < 4; q++) c[j][q] = 0.f;
#pragma unroll 4
        for (int ks = 0; ks < 16; ks++) {
            int k0 = ks * 8;
            uint32_t A[4];
            A[0] = f2tf32(s_h[r * 132 + k0 + cc]);
            A[1] = f2tf32(s_h[(r + 8) * 132 + k0 + cc]);
            A[2] = f2tf32(s_h[r * 132 + k0 + cc + 4]);
            A[3] = f2tf32(s_h[(r + 8) * 132 + k0 + cc + 4]);
#pragma unroll
            for (int j = 0; j < 6; j++) {
                uint2 b = Bb[(j * 16 + ks) * 32];
                mma_tf32(c[j], A, b);
            }
        }
#pragma unroll
        for (int j = 0; j < 6; j++) {
            int col = wid * 48 + j * 8 + 2 * cc;
            *(float2*)&s_gh[r * 392 + col] = make_float2(c[j][0], c[j][1]);
            *(float2*)&s_gh[(r + 8) * 392 + col] = make_float2(c[j][2], c[j][3]);
        }
        __syncthreads();
#pragma unroll
        for (int p = 0; p < 8; p++) {
            int s = sblk * 8 + p;
            float ghr = s_gh[s * 392 + dd];
            float ghz = s_gh[s * 392 + DD + dd];
            float ghn = s_gh[s * 392 + 2 * DD + dd];
            float h = s_h[s * 132 + dd];
            float rr = sigf(xr[p] + ghr + br);
            float zz = sigf(xz[p] + ghz + bz);
            float nn = tanhf(xn[p] + rr * (ghn + bn));
            s_h[s * 132 + dd] = (1.f - zz) * nn + zz * h;
        }
        __syncthreads();
    }
    for (int i = tid; i < 16 * DD; i += 256) {
        int s = i >> 7, d = i & 127;
        g_h5[(key * BV + n0 + s) * DD + d] = s_h[s * 132 + d];
    }
}

// ---------------- K5: visit input-gates (R2 version) ---------------------------
__global__ void __launch_bounds__(384) k_vxg(const float* weight, const float* age,
                                             const float* info_w, const float* info_b,
                                             const float* bih) {
    __shared__ float sx[16 * DD];
    int key = blockIdx.y, b = blockIdx.x, g = threadIdx.x;
    for (int i = g; i < 16 * DD; i += GG) {
        int v = i / DD, d = i % DD;
        float x;
        if (key < 5)       x = g_h5[(key * BV + b * 16 + v) * DD + d];
        else if (key == 5) x = weight[b * 16 + v] * info_w[d] + info_b[d];
        else               x = age[b * 16 + v] * info_w[DD + d] + info_b[DD + d];
        sx[i] = x;
    }
    __syncthreads();
    float bb = bih[key * GG + g];
    float acc[16];
#pragma unroll
    for (int v = 0; v < 16; v++) acc[v] = bb;
    const float* w = &g_wT[WIH_V + key * (DD * GG) + g];
    for (int d = 0; d < DD; d++) {
        float wv = w[d * GG];
#pragma unroll
        for (int v = 0; v < 16; v++) acc[v] += wv * sx[v * DD + d];
    }
    float* out = &g_vxg[((key * 16 + b) * 16) * GG + g];
#pragma unroll
    for (int v = 0; v < 16; v++) out[v * GG] = acc[v];
}

// ---------------- K6: visit GRU recurrence -------------------------------------
// grid (16, 7), block 384, dyn smem = (DD*GG + DD + GG)*4 = 198656 B
__global__ void __launch_bounds__(384) k_vis_gru(const float* bhh) {
    extern __shared__ float sm[];
    float* s_w = sm;
    float* s_h = sm + DD * GG;
    float* s_gh = s_h + DD;
    int key = blockIdx.y, b = blockIdx.x, g = threadIdx.x;
    for (int i = g; i < DD * GG; i += GG) s_w[i] = g_wT[WHH_V + key * (DD * GG) + i];
    if (g < DD) s_h[g] = 0.f;
    __syncthreads();
    float bb = bhh[key * GG + g];
    for (int t = 0; t < 16; t++) {
        float acc = bb;
#pragma unroll 4
        for (int d = 0; d < DD; d++) acc += s_w[d * GG + g] * s_h[d];
        s_gh[g] = acc;
        __syncthreads();
        if (g < DD) {
            const float* xg = &g_vxg[((key * 16 + b) * 16 + t) * GG];
            float r = sigf(xg[g] + s_gh[g]);
            float z = sigf(xg[DD + g] + s_gh[DD + g]);
            float nn = tanhf(xg[2 * DD + g] + r * s_gh[2 * DD + g]);
            s_h[g] = (1.f - z) * nn + z * s_h[g];
        }
        __syncthreads();
    }
    if (g < DD) g_hv[(key * 16 + b) * DD + g] = s_h[g];
}

// ---------------- K7: ReLU + final FC --------------------------------------------
__global__ void k_fc(const float* fcw, const float* fcb, float* out) {
    __shared__ float pe[7 * DD];
    int b = blockIdx.x, o = threadIdx.x;
    for (int i = o; i < 7 * DD; i += 256) {
        int k = i / DD, d = i % DD;
        pe[i] = fmaxf(g_hv[(k * 16 + b) * DD + d], 0.f);
    }
    __syncthreads();
    if (o < NOUT) {
        float acc = fcb[o];
        for (int j = 0; j < 7 * DD; j++) acc += pe[j] * fcw[j * NOUT + o];
        out[b * NOUT + o] = acc;
    }
}

// ---------------- launch -----------------------------------------------------------
extern "C" void kernel_launch(void* const* d_in, const int* in_sizes, int n_in,
                              void* d_out, int out_size) {
    const int* tok_cond      = (const int*)d_in[0];
    const int* tok_proc      = (const int*)d_in[1];
    const int* tok_drug      = (const int*)d_in[2];
    const int* tok_lab_item  = (const int*)d_in[3];
    const int* tok_lab_value = (const int*)d_in[4];
    const int* tok_inj_item  = (const int*)d_in[5];
    const int* tok_inj_value = (const int*)d_in[6];
    const float* weight      = (const float*)d_in[7];
    const float* age         = (const float*)d_in[8];
    const float* emb_cond    = (const float*)d_in[9];
    const float* emb_proc    = (const float*)d_in[10];
    const float* emb_drug    = (const float*)d_in[11];
    const float* emb_li      = (const float*)d_in[12];
    const float* emb_lv      = (const float*)d_in[13];
    const float* emb_ii      = (const float*)d_in[14];
    const float* emb_iv      = (const float*)d_in[15];
    const float* mgru_wih    = (const float*)d_in[16];
    const float* mgru_whh    = (const float*)d_in[17];
    const float* mgru_bih    = (const float*)d_in[18];
    const float* mgru_bhh    = (const float*)d_in[19];
    const float* vgru_wih    = (const float*)d_in[20];
    const float* vgru_whh    = (const float*)d_in[21];
    const float* vgru_bih    = (const float*)d_in[22];
    const float* vgru_bhh    = (const float*)d_in[23];
    const float* info_w      = (const float*)d_in[24];
    const float* info_b      = (const float*)d_in[25];
    const float* fc_w        = (const float*)d_in[26];
    const float* fc_b        = (const float*)d_in[27];
    float* out = (float*)d_out;

    cudaFuncSetAttribute(k_mon_gru, cudaFuncAttributeMaxDynamicSharedMemorySize, 230144);
    cudaFuncSetAttribute(k_vis_gru, cudaFuncAttributeMaxDynamicSharedMemorySize, 198656);

    k_transpose<<<dim3(384, 17), 128>>>(mgru_wih, vgru_wih, vgru_whh);
    k_packB34<<<192, 256>>>(mgru_wih);
    k_packBhh<<<480, 256>>>(mgru_whh);
    k_embed_visit<<<dim3(256, 3), 128>>>(tok_cond, tok_proc, tok_drug,
                                         emb_cond, emb_proc, emb_drug);
    k_embed_mon<<<dim3(2048, 2), 128>>>(tok_lab_item, tok_lab_value,
                                        tok_inj_item, tok_inj_value,
                                        emb_li, emb_lv, emb_ii, emb_iv);
    k_xg34_mma<<<dim3(256, 2), 256>>>(mgru_bih);
    k_xg012<<<dim3(256, 3), 384>>>(mgru_bih);
    k_mon_gru<<<dim3(16, 5), 256, 230144>>>(mgru_bhh);
    k_vxg<<<dim3(16, 7), 384>>>(weight, age, info_w, info_b, vgru_bih);
    k_vis_gru<<<dim3(16, 7), 384, 198656>>>(vgru_bhh);
    k_fc<<<16, 256>>>(fc_w, fc_b, out);
}

// round 12
// speedup vs baseline: 1.9795x; 1.1470x over previous
#include <cuda_runtime.h>
#include <cstdint>

#define DD 128
#define GG 384
#define BV 256
#define MM 32
#define LL 24
#define NOUT 193

// ---------------- scratch (static device globals; no allocation) -------------
__device__ float g_mon[2 * BV * MM * DD];      // lab / inj monitor embeddings
__device__ float g_xg34[2 * BV * MM * GG];     // monitor input-gates, keys 3,4
__device__ float g_xg012[3 * BV * GG];         // monitor input-gates, keys 0-2 (t-invariant)
__device__ float g_h5[5 * BV * DD];            // monitor final hidden
__device__ float g_hv[7 * 16 * DD];            // visit final hidden
__device__ float g_wT[24 * DD * GG];           // transposed weights [d][g] (slices 0-2,10-23)
__device__ uint2 g_wB34[2 * 48 * 16 * 32];     // tf32 B fragments: mgru_wih keys 3,4
__device__ uint2 g_wBhh[5 * 48 * 16 * 32];     // tf32 B fragments: mgru_whh keys 0..4

#define WIH_M 0
#define WIH_V (10 * DD * GG)
#define WHH_V (17 * DD * GG)

__device__ __forceinline__ float sigf(float x) { return 1.0f / (1.0f + __expf(-x)); }

__device__ __forceinline__ uint32_t f2tf32(float x) {
    uint32_t u; asm("cvt.rna.tf32.f32 %0, %1;" : "=r"(u) : "f"(x)); return u;
}
__device__ __forceinline__ void mma_tf32(float* c, const uint32_t* a, uint2 b) {
    asm volatile("mma.sync.aligned.m16n8k8.row.col.f32.tf32.tf32.f32 "
                 "{%0,%1,%2,%3}, {%4,%5,%6,%7}, {%8,%9}, {%0,%1,%2,%3};"
                 : "+f"(c[0]), "+f"(c[1]), "+f"(c[2]), "+f"(c[3])
                 : "r"(a[0]), "r"(a[1]), "r"(a[2]), "r"(a[3]), "r"(b.x), "r"(b.y));
}

// ---------------- K_prep: fused weight transpose + tf32 fragment packs --------
__global__ void __launch_bounds__(256) k_prep(const float* __restrict__ mih,
                                              const float* __restrict__ mhh,
                                              const float* __restrict__ vih,
                                              const float* __restrict__ vhh) {
    int b = blockIdx.x, tid = threadIdx.x;
    if (b < 3264) {
        int i = b * 256 + tid;          // < 835584
        int yy = i / 49152;             // 0..16
        int r  = i % 49152;             // d*384+g
        int d = r / GG, g = r % GG;
        const float* src; int k, slice;
        if (yy < 3)       { src = mih; k = yy;      slice = yy; }
        else if (yy < 10) { src = vih; k = yy - 3;  slice = 10 + (yy - 3); }
        else              { src = vhh; k = yy - 10; slice = 17 + (yy - 10); }
        g_wT[slice * 49152 + r] = src[(k * GG + g) * DD + d];
    } else if (b < 3456) {
        int idx = (b - 3264) * 256 + tid;   // < 49152
        int lane = idx & 31;
        int ks = (idx >> 5) & 15;
        int tmp = idx >> 9;
        int pair = tmp / 48, nt = tmp % 48;
        int n = nt * 8 + (lane >> 2);
        int k = ks * 8 + (lane & 3);
        const float* W = mih + (3 + pair) * (GG * DD);
        uint2 o;
        o.x = f2tf32(W[n * DD + k]);
        o.y = f2tf32(W[n * DD + k + 4]);
        g_wB34[idx] = o;
    } else {
        int idx = (b - 3456) * 256 + tid;   // < 122880
        int lane = idx & 31;
        int ks = (idx >> 5) & 15;
        int tmp = idx >> 9;
        int key = tmp / 48, nt = tmp % 48;
        int n = nt * 8 + (lane >> 2);
        int k = ks * 8 + (lane & 3);
        const float* W = mhh + key * (GG * DD);
        uint2 o;
        o.x = f2tf32(W[n * DD + k]);
        o.y = f2tf32(W[n * DD + k + 4]);
        g_wBhh[idx] = o;
    }
}

// ---------------- K2: monitor-event pair embedding sums (float4) -------------
__global__ void k_embed_mon(const int* __restrict__ tli, const int* __restrict__ tlv,
                            const int* __restrict__ tii, const int* __restrict__ tiv,
                            const float* __restrict__ eli, const float* __restrict__ elv,
                            const float* __restrict__ eii, const float* __restrict__ eiv) {
    int pair = blockIdx.y;
    int r = blockIdx.x * 4 + (threadIdx.x >> 5);   // monitor row 0..8191
    int lane = threadIdx.x & 31;
    const int* ti = pair ? tii : tli;
    const int* tv = pair ? tiv : tlv;
    const float4* ei = (const float4*)(pair ? eii : eli);
    const float4* ev = (const float4*)(pair ? eiv : elv);
    float4 acc = make_float4(0.f, 0.f, 0.f, 0.f);
#pragma unroll
    for (int l = 0; l < LL; l++) {
        int a = ti[r * LL + l];
        int b = tv[r * LL + l];
        float4 x = ei[a * 32 + lane];
        float4 y = ev[b * 32 + lane];
        acc.x += x.x * y.x; acc.y += x.y * y.y;
        acc.z += x.z * y.z; acc.w += x.w * y.w;
    }
    ((float4*)g_mon)[(pair * 8192 + r) * 32 + lane] = acc;
}

// ---------------- K3a: monitor input-gates keys 3,4 — tf32 mma.sync -----------
__global__ void __launch_bounds__(256) k_xg34_mma(const float* __restrict__ bih) {
    __shared__ float sX[32 * 132];
    int pair = blockIdx.y, n = blockIdx.x, key = 3 + pair;
    int tid = threadIdx.x, lane = tid & 31, wid = tid >> 5;
    const float* xsrc = &g_mon[(pair * BV + n) * MM * DD];
    for (int i = tid; i < 32 * 128; i += 256)
        sX[(i >> 7) * 132 + (i & 127)] = xsrc[i];
    __syncthreads();
    int r = lane >> 2, cc = lane & 3;
    float c[2][6][4];
#pragma unroll
    for (int m = 0; m < 2; m++)
#pragma unroll
        for (int j = 0; j < 6; j++)
#pragma unroll
            for (int q = 0; q < 4; q++) c[m][j][q] = 0.f;
    const uint2* Bbase = &g_wB34[((pair * 48 + wid * 6) * 16) * 32 + lane];
#pragma unroll 4
    for (int ks = 0; ks < 16; ks++) {
        int k0 = ks * 8;
        uint32_t A[2][4];
#pragma unroll
        for (int m = 0; m < 2; m++) {
            int row = m * 16 + r;
            A[m][0] = f2tf32(sX[row * 132 + k0 + cc]);
            A[m][1] = f2tf32(sX[(row + 8) * 132 + k0 + cc]);
            A[m][2] = f2tf32(sX[row * 132 + k0 + cc + 4]);
            A[m][3] = f2tf32(sX[(row + 8) * 132 + k0 + cc + 4]);
        }
#pragma unroll
        for (int j = 0; j < 6; j++) {
            uint2 b = Bbase[(j * 16 + ks) * 32];
            mma_tf32(c[0][j], A[0], b);
            mma_tf32(c[1][j], A[1], b);
        }
    }
    float* outbase = &g_xg34[((pair * BV + n) * MM) * GG];
#pragma unroll
    for (int j = 0; j < 6; j++) {
        int col = wid * 48 + j * 8 + 2 * cc;
        float2 bias = *(const float2*)&bih[key * GG + col];
#pragma unroll
        for (int m = 0; m < 2; m++) {
            int row0 = m * 16 + r;
            float2 v0 = make_float2(c[m][j][0] + bias.x, c[m][j][1] + bias.y);
            float2 v1 = make_float2(c[m][j][2] + bias.x, c[m][j][3] + bias.y);
            *(float2*)&outbase[row0 * GG + col] = v0;
            *(float2*)&outbase[(row0 + 8) * GG + col] = v1;
        }
    }
}

// ---------------- K3b: fused visit-embedding + input-gates keys 0-2 -----------
__global__ void __launch_bounds__(384) k_embed_xg012(
        const int* __restrict__ tc, const int* __restrict__ tp, const int* __restrict__ td,
        const float* __restrict__ ec, const float* __restrict__ ep, const float* __restrict__ ed,
        const float* __restrict__ bih) {
    __shared__ float sx[DD];
    int key = blockIdx.y, n = blockIdx.x, g = threadIdx.x;
    if (g < DD) {
        const int* tok = (key == 0) ? tc : (key == 1) ? tp : td;
        const float* emb = (key == 0) ? ec : (key == 1) ? ep : ed;
        float acc = 0.f;
#pragma unroll
        for (int l = 0; l < LL; l++) acc += emb[tok[n * LL + l] * DD + g];
        sx[g] = acc;
    }
    __syncthreads();
    float acc = bih[key * GG + g];
    const float* w = &g_wT[WIH_M + key * (DD * GG) + g];
#pragma unroll 4
    for (int d = 0; d < DD; d++) acc += w[d * GG] * sx[d];
    g_xg012[(key * BV + n) * GG + g] = acc;
}

// ---------------- K4: monitor GRU recurrence — tf32 mma dot phase -------------
// grid (16, 5), block 256 (8 warps), dyn smem = 230144 B
__global__ void __launch_bounds__(256) k_mon_gru(const float* __restrict__ bhh) {
    extern __shared__ float sm[];
    uint2* s_wB = (uint2*)sm;                 // 196608 B
    float* s_h  = sm + 49152;                 // 16*132 floats
    float* s_gh = sm + 49152 + 16 * 132;      // 16*392 floats
    int key = blockIdx.y, grp = blockIdx.x;
    int tid = threadIdx.x, lane = tid & 31, wid = tid >> 5;
    int n0 = grp * 16;
    {
        const float4* src = (const float4*)(g_wBhh + key * 24576);
        float4* dst = (float4*)s_wB;
        for (int i = tid; i < 12288; i += 256) dst[i] = src[i];
    }
    for (int i = tid; i < 16 * 132; i += 256) s_h[i] = 0.f;
    __syncthreads();

    int sblk = tid >> 7, dd = tid & 127;
    float br = bhh[key * GG + dd];
    float bz = bhh[key * GG + DD + dd];
    float bn = bhh[key * GG + 2 * DD + dd];
    float xr[8], xz[8], xn[8];
    const float* xgp[8];
#pragma unroll
    for (int p = 0; p < 8; p++) {
        int n = n0 + sblk * 8 + p;
        if (key < 3) {
            const float* xg = &g_xg012[(key * BV + n) * GG];
            xr[p] = xg[dd]; xz[p] = xg[DD + dd]; xn[p] = xg[2 * DD + dd];
            xgp[p] = nullptr;
        } else {
            xgp[p] = &g_xg34[(((key - 3) * BV + n) * MM) * GG];
        }
    }

    int r = lane >> 2, cc = lane & 3;
    const uint2* Bb = s_wB + (wid * 6 * 16) * 32 + lane;

    for (int t = 0; t < MM; t++) {
        if (key >= 3) {
#pragma unroll
            for (int p = 0; p < 8; p++) {
                const float* xg = xgp[p] + t * GG;
                xr[p] = __ldg(xg + dd);
                xz[p] = __ldg(xg + DD + dd);
                xn[p] = __ldg(xg + 2 * DD + dd);
            }
        }
        float c[6][4];
#pragma unroll
        for (int j = 0; j < 6; j++)
#pragma unroll
            for (int q = 0; q < 4; q++) c[j][q] = 0.f;
#pragma unroll 4
        for (int ks = 0; ks < 16; ks++) {
            int k0 = ks * 8;
            uint32_t A[4];
            A[0] = f2tf32(s_h[r * 132 + k0 + cc]);
            A[1] = f2tf32(s_h[(r + 8) * 132 + k0 + cc]);
            A[2] = f2tf32(s_h[r * 132 + k0 + cc + 4]);
            A[3] = f2tf32(s_h[(r + 8) * 132 + k0 + cc + 4]);
#pragma unroll
            for (int j = 0; j < 6; j++) {
                uint2 b = Bb[(j * 16 + ks) * 32];
                mma_tf32(c[j], A, b);
            }
        }
#pragma unroll
        for (int j = 0; j < 6; j++) {
            int col = wid * 48 + j * 8 + 2 * cc;
            *(float2*)&s_gh[r * 392 + col] = make_float2(c[j][0], c[j][1]);
            *(float2*)&s_gh[(r + 8) * 392 + col] = make_float2(c[j][2], c[j][3]);
        }
        __syncthreads();
#pragma unroll
        for (int p = 0; p < 8; p++) {
            int s = sblk * 8 + p;
            float ghr = s_gh[s * 392 + dd];
            float ghz = s_gh[s * 392 + DD + dd];
            float ghn = s_gh[s * 392 + 2 * DD + dd];
            float h = s_h[s * 132 + dd];
            float rr = sigf(xr[p] + ghr + br);
            float zz = sigf(xz[p] + ghz + bz);
            float nn = tanhf(xn[p] + rr * (ghn + bn));
            s_h[s * 132 + dd] = (1.f - zz) * nn + zz * h;
        }
        __syncthreads();
    }
    for (int i = tid; i < 16 * DD; i += 256) {
        int s = i >> 7, d = i & 127;
        g_h5[(key * BV + n0 + s) * DD + d] = s_h[s * 132 + d];
    }
}

// ---------------- K5+K6 fused: visit input-gates + visit GRU recurrence -------
__global__ void __launch_bounds__(384) k_vxg_vis(
        const float* __restrict__ weight, const float* __restrict__ age,
        const float* __restrict__ info_w, const float* __restrict__ info_b,
        const float* __restrict__ bih, const float* __restrict__ bhh) {
    extern __shared__ float sm[];
    float* s_w  = sm;                   // 49152
    float* s_xg = sm + 49152;           // 6208
    float* s_h  = s_xg + 6208;          // 128
    float* s_gh = s_h + 128;            // 384
    float* sx   = s_xg;                 // alias (2048 floats) during phase 1-2
    int key = blockIdx.y, b = blockIdx.x, g = threadIdx.x;
    // phase 1: gather x [16][128]
    for (int i = g; i < 16 * DD; i += GG) {
        int v = i / DD, d = i % DD;
        float x;
        if (key < 5)       x = g_h5[(key * BV + b * 16 + v) * DD + d];
        else if (key == 5) x = weight[b * 16 + v] * info_w[d] + info_b[d];
        else               x = age[b * 16 + v] * info_w[DD + d] + info_b[DD + d];
        sx[i] = x;
    }
    __syncthreads();
    // phase 2: input-gate dot (Wih_v streamed from L2)
    float bb = bih[key * GG + g];
    float acc[16];
#pragma unroll
    for (int v = 0; v < 16; v++) acc[v] = bb;
    {
        const float* w = &g_wT[WIH_V + key * (DD * GG) + g];
        for (int d = 0; d < DD; d++) {
            float wv = w[d * GG];
#pragma unroll
            for (int v = 0; v < 16; v++) acc[v] += wv * sx[v * DD + d];
        }
    }
    __syncthreads();
    // phase 3: stage gates to smem; load Whh_v; init h
#pragma unroll
    for (int v = 0; v < 16; v++) s_xg[v * 388 + g] = acc[v];
    {
        const float4* src = (const float4*)&g_wT[WHH_V + key * (DD * GG)];
        float4* dst = (float4*)s_w;
        for (int i = g; i < 12288; i += GG) dst[i] = src[i];
    }
    if (g < DD) s_h[g] = 0.f;
    float bh = bhh[key * GG + g];
    __syncthreads();
    // phase 4: 16-step recurrence
    for (int t = 0; t < 16; t++) {
        float a = bh;
#pragma unroll 4
        for (int d = 0; d < DD; d++) a += s_w[d * GG + g] * s_h[d];
        s_gh[g] = a;
        __syncthreads();
        if (g < DD) {
            const float* xg = &s_xg[t * 388];
            float r = sigf(xg[g] + s_gh[g]);
            float z = sigf(xg[DD + g] + s_gh[DD + g]);
            float nn = tanhf(xg[2 * DD + g] + r * s_gh[2 * DD + g]);
            s_h[g] = (1.f - z) * nn + z * s_h[g];
        }
        __syncthreads();
    }
    if (g < DD) g_hv[(key * 16 + b) * DD + g] = s_h[g];
}

// ---------------- K7: ReLU + final FC --------------------------------------------
__global__ void k_fc(const float* fcw, const float* fcb, float* out) {
    __shared__ float pe[7 * DD];
    int b = blockIdx.x, o = threadIdx.x;
    for (int i = o; i < 7 * DD; i += 256) {
        int k = i / DD, d = i % DD;
        pe[i] = fmaxf(g_hv[(k * 16 + b) * DD + d], 0.f);
    }
    __syncthreads();
    if (o < NOUT) {
        float acc = fcb[o];
        for (int j = 0; j < 7 * DD; j++) acc += pe[j] * fcw[j * NOUT + o];
        out[b * NOUT + o] = acc;
    }
}

// ---------------- launch -----------------------------------------------------------
extern "C" void kernel_launch(void* const* d_in, const int* in_sizes, int n_in,
                              void* d_out, int out_size) {
    const int* tok_cond      = (const int*)d_in[0];
    const int* tok_proc      = (const int*)d_in[1];
    const int* tok_drug      = (const int*)d_in[2];
    const int* tok_lab_item  = (const int*)d_in[3];
    const int* tok_lab_value = (const int*)d_in[4];
    const int* tok_inj_item  = (const int*)d_in[5];
    const int* tok_inj_value = (const int*)d_in[6];
    const float* weight      = (const float*)d_in[7];
    const float* age         = (const float*)d_in[8];
    const float* emb_cond    = (const float*)d_in[9];
    const float* emb_proc    = (const float*)d_in[10];
    const float* emb_drug    = (const float*)d_in[11];
    const float* emb_li      = (const float*)d_in[12];
    const float* emb_lv      = (const float*)d_in[13];
    const float* emb_ii      = (const float*)d_in[14];
    const float* emb_iv      = (const float*)d_in[15];
    const float* mgru_wih    = (const float*)d_in[16];
    const float* mgru_whh    = (const float*)d_in[17];
    const float* mgru_bih    = (const float*)d_in[18];
    const float* mgru_bhh    = (const float*)d_in[19];
    const float* vgru_wih    = (const float*)d_in[20];
    const float* vgru_whh    = (const float*)d_in[21];
    const float* vgru_bih    = (const float*)d_in[22];
    const float* vgru_bhh    = (const float*)d_in[23];
    const float* info_w      = (const float*)d_in[24];
    const float* info_b      = (const float*)d_in[25];
    const float* fc_w        = (const float*)d_in[26];
    const float* fc_b        = (const float*)d_in[27];
    float* out = (float*)d_out;

    cudaFuncSetAttribute(k_mon_gru, cudaFuncAttributeMaxDynamicSharedMemorySize, 230144);
    cudaFuncSetAttribute(k_vxg_vis, cudaFuncAttributeMaxDynamicSharedMemorySize, 223488);

    // Streams/events created ONCE on the first call (the correctness run, before
    // the harness takes its pre-capture memory baseline) and reused for every
    // subsequent call. Nothing is created or destroyed during capture/replay, so
    // device memory stays at baseline through graph teardown. The captured graph
    // is identical on every call (same nodes, same dependency structure).
    static cudaStream_t sA = nullptr, sB = nullptr;
    static cudaEvent_t eF = nullptr, eA = nullptr, eB = nullptr;
    if (sA == nullptr) {
        cudaStreamCreateWithFlags(&sA, cudaStreamNonBlocking);
        cudaStreamCreateWithFlags(&sB, cudaStreamNonBlocking);
        cudaEventCreateWithFlags(&eF, cudaEventDisableTiming);
        cudaEventCreateWithFlags(&eA, cudaEventDisableTiming);
        cudaEventCreateWithFlags(&eB, cudaEventDisableTiming);
    }

    cudaEventRecord(eF, 0);
    cudaStreamWaitEvent(sA, eF, 0);

    // stream A: weight prep (transpose + tf32 packs)
    k_prep<<<3936, 256, 0, sA>>>(mgru_wih, mgru_whh, vgru_wih, vgru_whh);
    cudaEventRecord(eA, sA);

    // stream B: visit embeddings + xg for keys 0-2 (needs transposed WIH_M)
    cudaStreamWaitEvent(sB, eA, 0);
    k_embed_xg012<<<dim3(256, 3), 384, 0, sB>>>(tok_cond, tok_proc, tok_drug,
                                                emb_cond, emb_proc, emb_drug, mgru_bih);
    cudaEventRecord(eB, sB);

    // main stream: monitor chain
    k_embed_mon<<<dim3(2048, 2), 128>>>(tok_lab_item, tok_lab_value,
                                        tok_inj_item, tok_inj_value,
                                        emb_li, emb_lv, emb_ii, emb_iv);
    cudaStreamWaitEvent(0, eA, 0);
    k_xg34_mma<<<dim3(256, 2), 256>>>(mgru_bih);
    cudaStreamWaitEvent(0, eB, 0);
    k_mon_gru<<<dim3(16, 5), 256, 230144>>>(mgru_bhh);
    k_vxg_vis<<<dim3(16, 7), 384, 223488>>>(weight, age, info_w, info_b,
                                            vgru_bih, vgru_bhh);
    k_fc<<<16, 256>>>(fc_w, fc_b, out);
}

// round 13
// speedup vs baseline: 1.9973x; 1.0090x over previous
#include <cuda_runtime.h>
#include <cstdint>

#define DD 128
#define GG 384
#define BV 256
#define MM 32
#define LL 24
#define NOUT 193

// ---------------- scratch (static device globals; no allocation) -------------
__device__ float g_mon[2 * BV * MM * DD];      // lab / inj monitor embeddings
__device__ float g_xg34[2 * BV * MM * GG];     // monitor input-gates, keys 3,4
__device__ float g_xg012[3 * BV * GG];         // monitor input-gates, keys 0-2 (t-invariant)
__device__ float g_h5[5 * BV * DD];            // monitor final hidden
__device__ float g_hv[7 * 16 * DD];            // visit final hidden
__device__ float g_wT[24 * DD * GG];           // transposed weights [d][g] (slices 0-2,10-23)
__device__ uint2 g_wB34[2 * 48 * 16 * 32];     // tf32 B fragments: mgru_wih keys 3,4
__device__ uint2 g_wBhh[5 * 48 * 16 * 32];     // tf32 B fragments: mgru_whh keys 0..4

#define WIH_M 0
#define WIH_V (10 * DD * GG)
#define WHH_V (17 * DD * GG)

__device__ __forceinline__ float sigf(float x) { return 1.0f / (1.0f + __expf(-x)); }

__device__ __forceinline__ uint32_t f2tf32(float x) {
    uint32_t u; asm("cvt.rna.tf32.f32 %0, %1;" : "=r"(u) : "f"(x)); return u;
}
__device__ __forceinline__ void mma_tf32(float* c, const uint32_t* a, uint2 b) {
    asm volatile("mma.sync.aligned.m16n8k8.row.col.f32.tf32.tf32.f32 "
                 "{%0,%1,%2,%3}, {%4,%5,%6,%7}, {%8,%9}, {%0,%1,%2,%3};"
                 : "+f"(c[0]), "+f"(c[1]), "+f"(c[2]), "+f"(c[3])
                 : "r"(a[0]), "r"(a[1]), "r"(a[2]), "r"(a[3]), "r"(b.x), "r"(b.y));
}

// ---------------- K_prep: fused weight transpose + tf32 fragment packs --------
__global__ void __launch_bounds__(256) k_prep(const float* __restrict__ mih,
                                              const float* __restrict__ mhh,
                                              const float* __restrict__ vih,
                                              const float* __restrict__ vhh) {
    int b = blockIdx.x, tid = threadIdx.x;
    if (b < 3264) {
        int i = b * 256 + tid;          // < 835584
        int yy = i / 49152;             // 0..16
        int r  = i % 49152;             // d*384+g
        int d = r / GG, g = r % GG;
        const float* src; int k, slice;
        if (yy < 3)       { src = mih; k = yy;      slice = yy; }
        else if (yy < 10) { src = vih; k = yy - 3;  slice = 10 + (yy - 3); }
        else              { src = vhh; k = yy - 10; slice = 17 + (yy - 10); }
        g_wT[slice * 49152 + r] = src[(k * GG + g) * DD + d];
    } else if (b < 3456) {
        int idx = (b - 3264) * 256 + tid;   // < 49152
        int lane = idx & 31;
        int ks = (idx >> 5) & 15;
        int tmp = idx >> 9;
        int pair = tmp / 48, nt = tmp % 48;
        int n = nt * 8 + (lane >> 2);
        int k = ks * 8 + (lane & 3);
        const float* W = mih + (3 + pair) * (GG * DD);
        uint2 o;
        o.x = f2tf32(W[n * DD + k]);
        o.y = f2tf32(W[n * DD + k + 4]);
        g_wB34[idx] = o;
    } else {
        int idx = (b - 3456) * 256 + tid;   // < 122880
        int lane = idx & 31;
        int ks = (idx >> 5) & 15;
        int tmp = idx >> 9;
        int key = tmp / 48, nt = tmp % 48;
        int n = nt * 8 + (lane >> 2);
        int k = ks * 8 + (lane & 3);
        const float* W = mhh + key * (GG * DD);
        uint2 o;
        o.x = f2tf32(W[n * DD + k]);
        o.y = f2tf32(W[n * DD + k + 4]);
        g_wBhh[idx] = o;
    }
}

// ---------------- K2: monitor-event pair embedding sums (float4) -------------
__global__ void k_embed_mon(const int* __restrict__ tli, const int* __restrict__ tlv,
                            const int* __restrict__ tii, const int* __restrict__ tiv,
                            const float* __restrict__ eli, const float* __restrict__ elv,
                            const float* __restrict__ eii, const float* __restrict__ eiv) {
    int pair = blockIdx.y;
    int r = blockIdx.x * 4 + (threadIdx.x >> 5);   // monitor row 0..8191
    int lane = threadIdx.x & 31;
    const int* ti = pair ? tii : tli;
    const int* tv = pair ? tiv : tlv;
    const float4* ei = (const float4*)(pair ? eii : eli);
    const float4* ev = (const float4*)(pair ? eiv : elv);
    float4 acc = make_float4(0.f, 0.f, 0.f, 0.f);
#pragma unroll
    for (int l = 0; l < LL; l++) {
        int a = ti[r * LL + l];
        int b = tv[r * LL + l];
        float4 x = ei[a * 32 + lane];
        float4 y = ev[b * 32 + lane];
        acc.x += x.x * y.x; acc.y += x.y * y.y;
        acc.z += x.z * y.z; acc.w += x.w * y.w;
    }
    ((float4*)g_mon)[(pair * 8192 + r) * 32 + lane] = acc;
}

// ---------------- K3a: monitor input-gates keys 3,4 — tf32 mma, 2 seq/CTA -----
// grid (128, 2), block 256 (8 warps). Warp: n=48; CTA: 2 sequences (m=2x32).
// B fragments loaded once per ks and reused across 2 seq x 2 m-tiles.
__global__ void __launch_bounds__(256, 1) k_xg34_mma(const float* __restrict__ bih) {
    __shared__ float sX[2 * 32 * 132];
    int pair = blockIdx.y, bx = blockIdx.x, key = 3 + pair;
    int n0 = bx * 2;
    int tid = threadIdx.x, lane = tid & 31, wid = tid >> 5;
    const float* xsrc = &g_mon[(pair * BV + n0) * MM * DD];
    for (int i = tid; i < 2 * 32 * 128; i += 256) {
        int sr = i >> 7, d = i & 127;          // sr = seq*32+row
        sX[sr * 132 + d] = xsrc[i];
    }
    __syncthreads();
    int r = lane >> 2, cc = lane & 3;
    float c[2][2][6][4];                        // [seq][mt][j][q]
#pragma unroll
    for (int s = 0; s < 2; s++)
#pragma unroll
        for (int m = 0; m < 2; m++)
#pragma unroll
            for (int j = 0; j < 6; j++)
#pragma unroll
                for (int q = 0; q < 4; q++) c[s][m][j][q] = 0.f;
    const uint2* Bbase = &g_wB34[((pair * 48 + wid * 6) * 16) * 32 + lane];
#pragma unroll 2
    for (int ks = 0; ks < 16; ks++) {
        int k0 = ks * 8;
        uint2 B[6];
#pragma unroll
        for (int j = 0; j < 6; j++) B[j] = Bbase[(j * 16 + ks) * 32];
#pragma unroll
        for (int s = 0; s < 2; s++) {
#pragma unroll
            for (int m = 0; m < 2; m++) {
                int row = s * 32 + m * 16 + r;
                uint32_t A[4];
                A[0] = f2tf32(sX[row * 132 + k0 + cc]);
                A[1] = f2tf32(sX[(row + 8) * 132 + k0 + cc]);
                A[2] = f2tf32(sX[row * 132 + k0 + cc + 4]);
                A[3] = f2tf32(sX[(row + 8) * 132 + k0 + cc + 4]);
#pragma unroll
                for (int j = 0; j < 6; j++) mma_tf32(c[s][m][j], A, B[j]);
            }
        }
    }
#pragma unroll
    for (int s = 0; s < 2; s++) {
        float* outbase = &g_xg34[((pair * BV + n0 + s) * MM) * GG];
#pragma unroll
        for (int j = 0; j < 6; j++) {
            int col = wid * 48 + j * 8 + 2 * cc;
            float2 bias = *(const float2*)&bih[key * GG + col];
#pragma unroll
            for (int m = 0; m < 2; m++) {
                int row0 = m * 16 + r;
                float2 v0 = make_float2(c[s][m][j][0] + bias.x, c[s][m][j][1] + bias.y);
                float2 v1 = make_float2(c[s][m][j][2] + bias.x, c[s][m][j][3] + bias.y);
                *(float2*)&outbase[row0 * GG + col] = v0;
                *(float2*)&outbase[(row0 + 8) * GG + col] = v1;
            }
        }
    }
}

// ---------------- K3b: fused visit-embedding + input-gates keys 0-2 -----------
__global__ void __launch_bounds__(384) k_embed_xg012(
        const int* __restrict__ tc, const int* __restrict__ tp, const int* __restrict__ td,
        const float* __restrict__ ec, const float* __restrict__ ep, const float* __restrict__ ed,
        const float* __restrict__ bih) {
    __shared__ float sx[DD];
    int key = blockIdx.y, n = blockIdx.x, g = threadIdx.x;
    if (g < DD) {
        const int* tok = (key == 0) ? tc : (key == 1) ? tp : td;
        const float* emb = (key == 0) ? ec : (key == 1) ? ep : ed;
        float acc = 0.f;
#pragma unroll
        for (int l = 0; l < LL; l++) acc += emb[tok[n * LL + l] * DD + g];
        sx[g] = acc;
    }
    __syncthreads();
    float acc = bih[key * GG + g];
    const float* w = &g_wT[WIH_M + key * (DD * GG) + g];
#pragma unroll 4
    for (int d = 0; d < DD; d++) acc += w[d * GG] * sx[d];
    g_xg012[(key * BV + n) * GG + g] = acc;
}

// ---------------- K4: monitor GRU recurrence — tf32 mma dot phase -------------
// grid (16, 5), block 256 (8 warps), dyn smem = 230144 B
__global__ void __launch_bounds__(256) k_mon_gru(const float* __restrict__ bhh) {
    extern __shared__ float sm[];
    uint2* s_wB = (uint2*)sm;                 // 196608 B
    float* s_h  = sm + 49152;                 // 16*132 floats
    float* s_gh = sm + 49152 + 16 * 132;      // 16*392 floats
    int key = blockIdx.y, grp = blockIdx.x;
    int tid = threadIdx.x, lane = tid & 31, wid = tid >> 5;
    int n0 = grp * 16;
    {
        const float4* src = (const float4*)(g_wBhh + key * 24576);
        float4* dst = (float4*)s_wB;
        for (int i = tid; i < 12288; i += 256) dst[i] = src[i];
    }
    for (int i = tid; i < 16 * 132; i += 256) s_h[i] = 0.f;
    __syncthreads();

    int sblk = tid >> 7, dd = tid & 127;
    float br = bhh[key * GG + dd];
    float bz = bhh[key * GG + DD + dd];
    float bn = bhh[key * GG + 2 * DD + dd];
    float xr[8], xz[8], xn[8];
    const float* xgp[8];
#pragma unroll
    for (int p = 0; p < 8; p++) {
        int n = n0 + sblk * 8 + p;
        if (key < 3) {
            const float* xg = &g_xg012[(key * BV + n) * GG];
            xr[p] = xg[dd]; xz[p] = xg[DD + dd]; xn[p] = xg[2 * DD + dd];
            xgp[p] = nullptr;
        } else {
            xgp[p] = &g_xg34[(((key - 3) * BV + n) * MM) * GG];
        }
    }

    int r = lane >> 2, cc = lane & 3;
    const uint2* Bb = s_wB + (wid * 6 * 16) * 32 + lane;

    for (int t = 0; t < MM; t++) {
        if (key >= 3) {
#pragma unroll
            for (int p = 0; p < 8; p++) {
                const float* xg = xgp[p] + t * GG;
                xr[p] = __ldg(xg + dd);
                xz[p] = __ldg(xg + DD + dd);
                xn[p] = __ldg(xg + 2 * DD + dd);
            }
        }
        float c[6][4];
#pragma unroll
        for (int j = 0; j < 6; j++)
#pragma unroll
            for (int q = 0; q < 4; q++) c[j][q] = 0.f;
#pragma unroll 4
        for (int ks = 0; ks < 16; ks++) {
            int k0 = ks * 8;
            uint32_t A[4];
            A[0] = f2tf32(s_h[r * 132 + k0 + cc]);
            A[1] = f2tf32(s_h[(r + 8) * 132 + k0 + cc]);
            A[2] = f2tf32(s_h[r * 132 + k0 + cc + 4]);
            A[3] = f2tf32(s_h[(r + 8) * 132 + k0 + cc + 4]);
#pragma unroll
            for (int j = 0; j < 6; j++) {
                uint2 b = Bb[(j * 16 + ks) * 32];
                mma_tf32(c[j], A, b);
            }
        }
#pragma unroll
        for (int j = 0; j < 6; j++) {
            int col = wid * 48 + j * 8 + 2 * cc;
            *(float2*)&s_gh[r * 392 + col] = make_float2(c[j][0], c[j][1]);
            *(float2*)&s_gh[(r + 8) * 392 + col] = make_float2(c[j][2], c[j][3]);
        }
        __syncthreads();
#pragma unroll
        for (int p = 0; p < 8; p++) {
            int s = sblk * 8 + p;
            float ghr = s_gh[s * 392 + dd];
            float ghz = s_gh[s * 392 + DD + dd];
            float ghn = s_gh[s * 392 + 2 * DD + dd];
            float h = s_h[s * 132 + dd];
            float rr = sigf(xr[p] + ghr + br);
            float zz = sigf(xz[p] + ghz + bz);
            float nn = tanhf(xn[p] + rr * (ghn + bn));
            s_h[s * 132 + dd] = (1.f - zz) * nn + zz * h;
        }
        __syncthreads();
    }
    for (int i = tid; i < 16 * DD; i += 256) {
        int s = i >> 7, d = i & 127;
        g_h5[(key * BV + n0 + s) * DD + d] = s_h[s * 132 + d];
    }
}

// ---------------- K5+K6 fused: visit input-gates + visit GRU recurrence -------
__global__ void __launch_bounds__(384) k_vxg_vis(
        const float* __restrict__ weight, const float* __restrict__ age,
        const float* __restrict__ info_w, const float* __restrict__ info_b,
        const float* __restrict__ bih, const float* __restrict__ bhh) {
    extern __shared__ float sm[];
    float* s_w  = sm;                   // 49152
    float* s_xg = sm + 49152;           // 6208
    float* s_h  = s_xg + 6208;          // 128
    float* s_gh = s_h + 128;            // 384
    float* sx   = s_xg;                 // alias (2048 floats) during phase 1-2
    int key = blockIdx.y, b = blockIdx.x, g = threadIdx.x;
    // phase 1: gather x [16][128]
    for (int i = g; i < 16 * DD; i += GG) {
        int v = i / DD, d = i % DD;
        float x;
        if (key < 5)       x = g_h5[(key * BV + b * 16 + v) * DD + d];
        else if (key == 5) x = weight[b * 16 + v] * info_w[d] + info_b[d];
        else               x = age[b * 16 + v] * info_w[DD + d] + info_b[DD + d];
        sx[i] = x;
    }
    __syncthreads();
    // phase 2: input-gate dot (Wih_v streamed from L2)
    float bb = bih[key * GG + g];
    float acc[16];
#pragma unroll
    for (int v = 0; v < 16; v++) acc[v] = bb;
    {
        const float* w = &g_wT[WIH_V + key * (DD * GG) + g];
        for (int d = 0; d < DD; d++) {
            float wv = w[d * GG];
#pragma unroll
            for (int v = 0; v < 16; v++) acc[v] += wv * sx[v * DD + d];
        }
    }
    __syncthreads();
    // phase 3: stage gates to smem; load Whh_v; init h
#pragma unroll
    for (int v = 0; v < 16; v++) s_xg[v * 388 + g] = acc[v];
    {
        const float4* src = (const float4*)&g_wT[WHH_V + key * (DD * GG)];
        float4* dst = (float4*)s_w;
        for (int i = g; i < 12288; i += GG) dst[i] = src[i];
    }
    if (g < DD) s_h[g] = 0.f;
    float bh = bhh[key * GG + g];
    __syncthreads();
    // phase 4: 16-step recurrence
    for (int t = 0; t < 16; t++) {
        float a = bh;
#pragma unroll 4
        for (int d = 0; d < DD; d++) a += s_w[d * GG + g] * s_h[d];
        s_gh[g] = a;
        __syncthreads();
        if (g < DD) {
            const float* xg = &s_xg[t * 388];
            float r = sigf(xg[g] + s_gh[g]);
            float z = sigf(xg[DD + g] + s_gh[DD + g]);
            float nn = tanhf(xg[2 * DD + g] + r * s_gh[2 * DD + g]);
            s_h[g] = (1.f - z) * nn + z * s_h[g];
        }
        __syncthreads();
    }
    if (g < DD) g_hv[(key * 16 + b) * DD + g] = s_h[g];
}

// ---------------- K7: ReLU + final FC --------------------------------------------
__global__ void k_fc(const float* fcw, const float* fcb, float* out) {
    __shared__ float pe[7 * DD];
    int b = blockIdx.x, o = threadIdx.x;
    for (int i = o; i < 7 * DD; i += 256) {
        int k = i / DD, d = i % DD;
        pe[i] = fmaxf(g_hv[(k * 16 + b) * DD + d], 0.f);
    }
    __syncthreads();
    if (o < NOUT) {
        float acc = fcb[o];
        for (int j = 0; j < 7 * DD; j++) acc += pe[j] * fcw[j * NOUT + o];
        out[b * NOUT + o] = acc;
    }
}

// ---------------- launch -----------------------------------------------------------
extern "C" void kernel_launch(void* const* d_in, const int* in_sizes, int n_in,
                              void* d_out, int out_size) {
    const int* tok_cond      = (const int*)d_in[0];
    const int* tok_proc      = (const int*)d_in[1];
    const int* tok_drug      = (const int*)d_in[2];
    const int* tok_lab_item  = (const int*)d_in[3];
    const int* tok_lab_value = (const int*)d_in[4];
    const int* tok_inj_item  = (const int*)d_in[5];
    const int* tok_inj_value = (const int*)d_in[6];
    const float* weight      = (const float*)d_in[7];
    const float* age         = (const float*)d_in[8];
    const float* emb_cond    = (const float*)d_in[9];
    const float* emb_proc    = (const float*)d_in[10];
    const float* emb_drug    = (const float*)d_in[11];
    const float* emb_li      = (const float*)d_in[12];
    const float* emb_lv      = (const float*)d_in[13];
    const float* emb_ii      = (const float*)d_in[14];
    const float* emb_iv      = (const float*)d_in[15];
    const float* mgru_wih    = (const float*)d_in[16];
    const float* mgru_whh    = (const float*)d_in[17];
    const float* mgru_bih    = (const float*)d_in[18];
    const float* mgru_bhh    = (const float*)d_in[19];
    const float* vgru_wih    = (const float*)d_in[20];
    const float* vgru_whh    = (const float*)d_in[21];
    const float* vgru_bih    = (const float*)d_in[22];
    const float* vgru_bhh    = (const float*)d_in[23];
    const float* info_w      = (const float*)d_in[24];
    const float* info_b      = (const float*)d_in[25];
    const float* fc_w        = (const float*)d_in[26];
    const float* fc_b        = (const float*)d_in[27];
    float* out = (float*)d_out;

    cudaFuncSetAttribute(k_mon_gru, cudaFuncAttributeMaxDynamicSharedMemorySize, 230144);
    cudaFuncSetAttribute(k_vxg_vis, cudaFuncAttributeMaxDynamicSharedMemorySize, 223488);

    // Streams/events created ONCE on the first call (before the harness's
    // pre-capture baseline) and reused forever; nothing created/destroyed
    // during capture/replay.
    static cudaStream_t sA = nullptr, sB = nullptr;
    static cudaEvent_t eF = nullptr, eA = nullptr, eB = nullptr;
    if (sA == nullptr) {
        cudaStreamCreateWithFlags(&sA, cudaStreamNonBlocking);
        cudaStreamCreateWithFlags(&sB, cudaStreamNonBlocking);
        cudaEventCreateWithFlags(&eF, cudaEventDisableTiming);
        cudaEventCreateWithFlags(&eA, cudaEventDisableTiming);
        cudaEventCreateWithFlags(&eB, cudaEventDisableTiming);
    }

    cudaEventRecord(eF, 0);
    cudaStreamWaitEvent(sA, eF, 0);

    // stream A: weight prep (transpose + tf32 packs)
    k_prep<<<3936, 256, 0, sA>>>(mgru_wih, mgru_whh, vgru_wih, vgru_whh);
    cudaEventRecord(eA, sA);

    // stream B: visit embeddings + xg for keys 0-2 (needs transposed WIH_M)
    cudaStreamWaitEvent(sB, eA, 0);
    k_embed_xg012<<<dim3(256, 3), 384, 0, sB>>>(tok_cond, tok_proc, tok_drug,
                                                emb_cond, emb_proc, emb_drug, mgru_bih);
    cudaEventRecord(eB, sB);

    // main stream: monitor chain
    k_embed_mon<<<dim3(2048, 2), 128>>>(tok_lab_item, tok_lab_value,
                                        tok_inj_item, tok_inj_value,
                                        emb_li, emb_lv, emb_ii, emb_iv);
    cudaStreamWaitEvent(0, eA, 0);
    k_xg34_mma<<<dim3(128, 2), 256>>>(mgru_bih);
    cudaStreamWaitEvent(0, eB, 0);
    k_mon_gru<<<dim3(16, 5), 256, 230144>>>(mgru_bhh);
    k_vxg_vis<<<dim3(16, 7), 384, 223488>>>(weight, age, info_w, info_b,
                                            vgru_bih, vgru_bhh);
    k_fc<<<16, 256>>>(fc_w, fc_b, out);
}

// round 14
// speedup vs baseline: 2.1950x; 1.0990x over previous
#include <cuda_runtime.h>
#include <cstdint>

#define DD 128
#define GG 384
#define BV 256
#define MM 32
#define LL 24
#define NOUT 193

// ---------------- scratch (static device globals; no allocation) -------------
__device__ float g_mon[2 * BV * MM * DD];      // lab / inj monitor embeddings
__device__ float g_xg34[2 * BV * MM * GG];     // monitor input-gates, keys 3,4
__device__ float g_xg012[3 * BV * GG];         // monitor input-gates, keys 0-2 (t-invariant)
__device__ float g_h5[5 * BV * DD];            // monitor final hidden
__device__ float g_hv[7 * 16 * DD];            // visit final hidden
__device__ float g_wT[24 * DD * GG];           // transposed weights [d][g] (slices 0-2,10-23)
__device__ uint2 g_wB34[2 * 48 * 16 * 32];     // tf32 B fragments: mgru_wih keys 3,4
__device__ uint2 g_wBhh[5 * 48 * 16 * 32];     // tf32 B fragments: mgru_whh keys 0..4

#define WIH_M 0
#define WIH_V (10 * DD * GG)
#define WHH_V (17 * DD * GG)

__device__ __forceinline__ float sigf(float x) { return 1.0f / (1.0f + __expf(-x)); }

__device__ __forceinline__ uint32_t f2tf32(float x) {
    uint32_t u; asm("cvt.rna.tf32.f32 %0, %1;" : "=r"(u) : "f"(x)); return u;
}
__device__ __forceinline__ void mma_tf32(float* c, const uint32_t* a, uint2 b) {
    asm volatile("mma.sync.aligned.m16n8k8.row.col.f32.tf32.tf32.f32 "
                 "{%0,%1,%2,%3}, {%4,%5,%6,%7}, {%8,%9}, {%0,%1,%2,%3};"
                 : "+f"(c[0]), "+f"(c[1]), "+f"(c[2]), "+f"(c[3])
                 : "r"(a[0]), "r"(a[1]), "r"(a[2]), "r"(a[3]), "r"(b.x), "r"(b.y));
}

// ---------------- K_prep: fused weight transpose + tf32 fragment packs --------
__global__ void __launch_bounds__(256) k_prep(const float* __restrict__ mih,
                                              const float* __restrict__ mhh,
                                              const float* __restrict__ vih,
                                              const float* __restrict__ vhh) {
    int b = blockIdx.x, tid = threadIdx.x;
    if (b < 3264) {
        int i = b * 256 + tid;          // < 835584
        int yy = i / 49152;             // 0..16
        int r  = i % 49152;             // d*384+g
        int d = r / GG, g = r % GG;
        const float* src; int k, slice;
        if (yy < 3)       { src = mih; k = yy;      slice = yy; }
        else if (yy < 10) { src = vih; k = yy - 3;  slice = 10 + (yy - 3); }
        else              { src = vhh; k = yy - 10; slice = 17 + (yy - 10); }
        g_wT[slice * 49152 + r] = src[(k * GG + g) * DD + d];
    } else if (b < 3456) {
        int idx = (b - 3264) * 256 + tid;   // < 49152
        int lane = idx & 31;
        int ks = (idx >> 5) & 15;
        int tmp = idx >> 9;
        int pair = tmp / 48, nt = tmp % 48;
        int n = nt * 8 + (lane >> 2);
        int k = ks * 8 + (lane & 3);
        const float* W = mih + (3 + pair) * (GG * DD);
        uint2 o;
        o.x = f2tf32(W[n * DD + k]);
        o.y = f2tf32(W[n * DD + k + 4]);
        g_wB34[idx] = o;
    } else {
        int idx = (b - 3456) * 256 + tid;   // < 122880
        int lane = idx & 31;
        int ks = (idx >> 5) & 15;
        int tmp = idx >> 9;
        int key = tmp / 48, nt = tmp % 48;
        int n = nt * 8 + (lane >> 2);
        int k = ks * 8 + (lane & 3);
        const float* W = mhh + key * (GG * DD);
        uint2 o;
        o.x = f2tf32(W[n * DD + k]);
        o.y = f2tf32(W[n * DD + k + 4]);
        g_wBhh[idx] = o;
    }
}

// ---------------- K2: monitor-event pair embedding sums (float4) -------------
__global__ void k_embed_mon(const int* __restrict__ tli, const int* __restrict__ tlv,
                            const int* __restrict__ tii, const int* __restrict__ tiv,
                            const float* __restrict__ eli, const float* __restrict__ elv,
                            const float* __restrict__ eii, const float* __restrict__ eiv) {
    int pair = blockIdx.y;
    int r = blockIdx.x * 4 + (threadIdx.x >> 5);   // monitor row 0..8191
    int lane = threadIdx.x & 31;
    const int* ti = pair ? tii : tli;
    const int* tv = pair ? tiv : tlv;
    const float4* ei = (const float4*)(pair ? eii : eli);
    const float4* ev = (const float4*)(pair ? eiv : elv);
    float4 acc = make_float4(0.f, 0.f, 0.f, 0.f);
#pragma unroll
    for (int l = 0; l < LL; l++) {
        int a = ti[r * LL + l];
        int b = tv[r * LL + l];
        float4 x = ei[a * 32 + lane];
        float4 y = ev[b * 32 + lane];
        acc.x += x.x * y.x; acc.y += x.y * y.y;
        acc.z += x.z * y.z; acc.w += x.w * y.w;
    }
    ((float4*)g_mon)[(pair * 8192 + r) * 32 + lane] = acc;
}

// ---------------- K3a: monitor input-gates keys 3,4 — tf32 mma, 2 seq/CTA -----
__global__ void __launch_bounds__(256, 1) k_xg34_mma(const float* __restrict__ bih) {
    __shared__ float sX[2 * 32 * 132];
    int pair = blockIdx.y, bx = blockIdx.x, key = 3 + pair;
    int n0 = bx * 2;
    int tid = threadIdx.x, lane = tid & 31, wid = tid >> 5;
    const float* xsrc = &g_mon[(pair * BV + n0) * MM * DD];
    for (int i = tid; i < 2 * 32 * 128; i += 256) {
        int sr = i >> 7, d = i & 127;          // sr = seq*32+row
        sX[sr * 132 + d] = xsrc[i];
    }
    __syncthreads();
    int r = lane >> 2, cc = lane & 3;
    float c[2][2][6][4];                        // [seq][mt][j][q]
#pragma unroll
    for (int s = 0; s < 2; s++)
#pragma unroll
        for (int m = 0; m < 2; m++)
#pragma unroll
            for (int j = 0; j < 6; j++)
#pragma unroll
                for (int q = 0; q < 4; q++) c[s][m][j][q] = 0.f;
    const uint2* Bbase = &g_wB34[((pair * 48 + wid * 6) * 16) * 32 + lane];
#pragma unroll 2
    for (int ks = 0; ks < 16; ks++) {
        int k0 = ks * 8;
        uint2 B[6];
#pragma unroll
        for (int j = 0; j < 6; j++) B[j] = Bbase[(j * 16 + ks) * 32];
#pragma unroll
        for (int s = 0; s < 2; s++) {
#pragma unroll
            for (int m = 0; m < 2; m++) {
                int row = s * 32 + m * 16 + r;
                uint32_t A[4];
                A[0] = f2tf32(sX[row * 132 + k0 + cc]);
                A[1] = f2tf32(sX[(row + 8) * 132 + k0 + cc]);
                A[2] = f2tf32(sX[row * 132 + k0 + cc + 4]);
                A[3] = f2tf32(sX[(row + 8) * 132 + k0 + cc + 4]);
#pragma unroll
                for (int j = 0; j < 6; j++) mma_tf32(c[s][m][j], A, B[j]);
            }
        }
    }
#pragma unroll
    for (int s = 0; s < 2; s++) {
        float* outbase = &g_xg34[((pair * BV + n0 + s) * MM) * GG];
#pragma unroll
        for (int j = 0; j < 6; j++) {
            int col = wid * 48 + j * 8 + 2 * cc;
            float2 bias = *(const float2*)&bih[key * GG + col];
#pragma unroll
            for (int m = 0; m < 2; m++) {
                int row0 = m * 16 + r;
                float2 v0 = make_float2(c[s][m][j][0] + bias.x, c[s][m][j][1] + bias.y);
                float2 v1 = make_float2(c[s][m][j][2] + bias.x, c[s][m][j][3] + bias.y);
                *(float2*)&outbase[row0 * GG + col] = v0;
                *(float2*)&outbase[(row0 + 8) * GG + col] = v1;
            }
        }
    }
}

// ---------------- K3b: fused visit-embedding + input-gates keys 0-2 -----------
__global__ void __launch_bounds__(384) k_embed_xg012(
        const int* __restrict__ tc, const int* __restrict__ tp, const int* __restrict__ td,
        const float* __restrict__ ec, const float* __restrict__ ep, const float* __restrict__ ed,
        const float* __restrict__ bih) {
    __shared__ float sx[DD];
    int key = blockIdx.y, n = blockIdx.x, g = threadIdx.x;
    if (g < DD) {
        const int* tok = (key == 0) ? tc : (key == 1) ? tp : td;
        const float* emb = (key == 0) ? ec : (key == 1) ? ep : ed;
        float acc = 0.f;
#pragma unroll
        for (int l = 0; l < LL; l++) acc += emb[tok[n * LL + l] * DD + g];
        sx[g] = acc;
    }
    __syncthreads();
    float acc = bih[key * GG + g];
    const float* w = &g_wT[WIH_M + key * (DD * GG) + g];
#pragma unroll 4
    for (int d = 0; d < DD; d++) acc += w[d * GG] * sx[d];
    g_xg012[(key * BV + n) * GG + g] = acc;
}

// ---------------- K4: monitor GRU recurrence — tf32 mma, 16 warps -------------
// grid (16, 5), block 512 (16 warps, 3 n-tiles each), dyn smem = 230144 B
__global__ void __launch_bounds__(512, 1) k_mon_gru(const float* __restrict__ bhh) {
    extern __shared__ float sm[];
    uint2* s_wB = (uint2*)sm;                 // 196608 B
    float* s_h  = sm + 49152;                 // 16*132 floats
    float* s_gh = sm + 49152 + 16 * 132;      // 16*392 floats
    int key = blockIdx.y, grp = blockIdx.x;
    int tid = threadIdx.x, lane = tid & 31, wid = tid >> 5;   // wid 0..15
    int n0 = grp * 16;
    {
        const float4* src = (const float4*)(g_wBhh + key * 24576);
        float4* dst = (float4*)s_wB;
        for (int i = tid; i < 12288; i += 512) dst[i] = src[i];
    }
    for (int i = tid; i < 16 * 132; i += 512) s_h[i] = 0.f;
    __syncthreads();

    // gate-phase mapping: thread owns 4 (s,d) pairs: s = sblk + 4p, d = dd
    int sblk = tid >> 7, dd = tid & 127;      // sblk 0..3
    float br = bhh[key * GG + dd];
    float bz = bhh[key * GG + DD + dd];
    float bn = bhh[key * GG + 2 * DD + dd];
    float xr[4], xz[4], xn[4];
    const float* xgp[4];
#pragma unroll
    for (int p = 0; p < 4; p++) {
        int n = n0 + sblk + p * 4;
        if (key < 3) {
            const float* xg = &g_xg012[(key * BV + n) * GG];
            xr[p] = xg[dd]; xz[p] = xg[DD + dd]; xn[p] = xg[2 * DD + dd];
            xgp[p] = nullptr;
        } else {
            xgp[p] = &g_xg34[(((key - 3) * BV + n) * MM) * GG];
        }
    }

    int r = lane >> 2, cc = lane & 3;
    const uint2* Bb = s_wB + (wid * 3 * 16) * 32 + lane;   // 3 j-tiles per warp

    for (int t = 0; t < MM; t++) {
        if (key >= 3) {
#pragma unroll
            for (int p = 0; p < 4; p++) {
                const float* xg = xgp[p] + t * GG;
                xr[p] = __ldg(xg + dd);
                xz[p] = __ldg(xg + DD + dd);
                xn[p] = __ldg(xg + 2 * DD + dd);
            }
        }
        float c[3][4];
#pragma unroll
        for (int j = 0; j < 3; j++)
#pragma unroll
            for (int q = 0; q < 4; q++) c[j][q] = 0.f;
#pragma unroll 4
        for (int ks = 0; ks < 16; ks++) {
            int k0 = ks * 8;
            uint32_t A[4];
            A[0] = f2tf32(s_h[r * 132 + k0 + cc]);
            A[1] = f2tf32(s_h[(r + 8) * 132 + k0 + cc]);
            A[2] = f2tf32(s_h[r * 132 + k0 + cc + 4]);
            A[3] = f2tf32(s_h[(r + 8) * 132 + k0 + cc + 4]);
#pragma unroll
            for (int j = 0; j < 3; j++) {
                uint2 b = Bb[(j * 16 + ks) * 32];
                mma_tf32(c[j], A, b);
            }
        }
#pragma unroll
        for (int j = 0; j < 3; j++) {
            int col = wid * 24 + j * 8 + 2 * cc;
            *(float2*)&s_gh[r * 392 + col] = make_float2(c[j][0], c[j][1]);
            *(float2*)&s_gh[(r + 8) * 392 + col] = make_float2(c[j][2], c[j][3]);
        }
        __syncthreads();
#pragma unroll
        for (int p = 0; p < 4; p++) {
            int s = sblk + p * 4;
            float ghr = s_gh[s * 392 + dd];
            float ghz = s_gh[s * 392 + DD + dd];
            float ghn = s_gh[s * 392 + 2 * DD + dd];
            float h = s_h[s * 132 + dd];
            float rr = sigf(xr[p] + ghr + br);
            float zz = sigf(xz[p] + ghz + bz);
            float nn = tanhf(xn[p] + rr * (ghn + bn));
            s_h[s * 132 + dd] = (1.f - zz) * nn + zz * h;
        }
        __syncthreads();
    }
    for (int i = tid; i < 16 * DD; i += 512) {
        int s = i >> 7, d = i & 127;
        g_h5[(key * BV + n0 + s) * DD + d] = s_h[s * 132 + d];
    }
}

// ---------------- K5+K6 fused: visit input-gates + visit GRU recurrence -------
__global__ void __launch_bounds__(384) k_vxg_vis(
        const float* __restrict__ weight, const float* __restrict__ age,
        const float* __restrict__ info_w, const float* __restrict__ info_b,
        const float* __restrict__ bih, const float* __restrict__ bhh) {
    extern __shared__ float sm[];
    float* s_w  = sm;                   // 49152
    float* s_xg = sm + 49152;           // 6208
    float* s_h  = s_xg + 6208;          // 128
    float* s_gh = s_h + 128;            // 384
    float* sx   = s_xg;                 // alias (2048 floats) during phase 1-2
    int key = blockIdx.y, b = blockIdx.x, g = threadIdx.x;
    // phase 1: gather x [16][128]
    for (int i = g; i < 16 * DD; i += GG) {
        int v = i / DD, d = i % DD;
        float x;
        if (key < 5)       x = g_h5[(key * BV + b * 16 + v) * DD + d];
        else if (key == 5) x = weight[b * 16 + v] * info_w[d] + info_b[d];
        else               x = age[b * 16 + v] * info_w[DD + d] + info_b[DD + d];
        sx[i] = x;
    }
    __syncthreads();
    // phase 2: input-gate dot (Wih_v streamed from L2)
    float bb = bih[key * GG + g];
    float acc[16];
#pragma unroll
    for (int v = 0; v < 16; v++) acc[v] = bb;
    {
        const float* w = &g_wT[WIH_V + key * (DD * GG) + g];
        for (int d = 0; d < DD; d++) {
            float wv = w[d * GG];
#pragma unroll
            for (int v = 0; v < 16; v++) acc[v] += wv * sx[v * DD + d];
        }
    }
    __syncthreads();
    // phase 3: stage gates to smem; load Whh_v; init h
#pragma unroll
    for (int v = 0; v < 16; v++) s_xg[v * 388 + g] = acc[v];
    {
        const float4* src = (const float4*)&g_wT[WHH_V + key * (DD * GG)];
        float4* dst = (float4*)s_w;
        for (int i = g; i < 12288; i += GG) dst[i] = src[i];
    }
    if (g < DD) s_h[g] = 0.f;
    float bh = bhh[key * GG + g];
    __syncthreads();
    // phase 4: 16-step recurrence
    for (int t = 0; t < 16; t++) {
        float a = bh;
#pragma unroll 4
        for (int d = 0; d < DD; d++) a += s_w[d * GG + g] * s_h[d];
        s_gh[g] = a;
        __syncthreads();
        if (g < DD) {
            const float* xg = &s_xg[t * 388];
            float r = sigf(xg[g] + s_gh[g]);
            float z = sigf(xg[DD + g] + s_gh[DD + g]);
            float nn = tanhf(xg[2 * DD + g] + r * s_gh[2 * DD + g]);
            s_h[g] = (1.f - z) * nn + z * s_h[g];
        }
        __syncthreads();
    }
    if (g < DD) g_hv[(key * 16 + b) * DD + g] = s_h[g];
}

// ---------------- K7: ReLU + final FC --------------------------------------------
__global__ void k_fc(const float* fcw, const float* fcb, float* out) {
    __shared__ float pe[7 * DD];
    int b = blockIdx.x, o = threadIdx.x;
    for (int i = o; i < 7 * DD; i += 256) {
        int k = i / DD, d = i % DD;
        pe[i] = fmaxf(g_hv[(k * 16 + b) * DD + d], 0.f);
    }
    __syncthreads();
    if (o < NOUT) {
        float acc = fcb[o];
        for (int j = 0; j < 7 * DD; j++) acc += pe[j] * fcw[j * NOUT + o];
        out[b * NOUT + o] = acc;
    }
}

// ---------------- launch -----------------------------------------------------------
extern "C" void kernel_launch(void* const* d_in, const int* in_sizes, int n_in,
                              void* d_out, int out_size) {
    const int* tok_cond      = (const int*)d_in[0];
    const int* tok_proc      = (const int*)d_in[1];
    const int* tok_drug      = (const int*)d_in[2];
    const int* tok_lab_item  = (const int*)d_in[3];
    const int* tok_lab_value = (const int*)d_in[4];
    const int* tok_inj_item  = (const int*)d_in[5];
    const int* tok_inj_value = (const int*)d_in[6];
    const float* weight      = (const float*)d_in[7];
    const float* age         = (const float*)d_in[8];
    const float* emb_cond    = (const float*)d_in[9];
    const float* emb_proc    = (const float*)d_in[10];
    const float* emb_drug    = (const float*)d_in[11];
    const float* emb_li      = (const float*)d_in[12];
    const float* emb_lv      = (const float*)d_in[13];
    const float* emb_ii      = (const float*)d_in[14];
    const float* emb_iv      = (const float*)d_in[15];
    const float* mgru_wih    = (const float*)d_in[16];
    const float* mgru_whh    = (const float*)d_in[17];
    const float* mgru_bih    = (const float*)d_in[18];
    const float* mgru_bhh    = (const float*)d_in[19];
    const float* vgru_wih    = (const float*)d_in[20];
    const float* vgru_whh    = (const float*)d_in[21];
    const float* vgru_bih    = (const float*)d_in[22];
    const float* vgru_bhh    = (const float*)d_in[23];
    const float* info_w      = (const float*)d_in[24];
    const float* info_b      = (const float*)d_in[25];
    const float* fc_w        = (const float*)d_in[26];
    const float* fc_b        = (const float*)d_in[27];
    float* out = (float*)d_out;

    cudaFuncSetAttribute(k_mon_gru, cudaFuncAttributeMaxDynamicSharedMemorySize, 230144);
    cudaFuncSetAttribute(k_vxg_vis, cudaFuncAttributeMaxDynamicSharedMemorySize, 223488);

    // Streams/events created ONCE on the first call (before the harness's
    // pre-capture baseline) and reused forever; nothing created/destroyed
    // during capture/replay.
    static cudaStream_t sA = nullptr, sB = nullptr;
    static cudaEvent_t eF = nullptr, eA = nullptr, eB = nullptr;
    if (sA == nullptr) {
        cudaStreamCreateWithFlags(&sA, cudaStreamNonBlocking);
        cudaStreamCreateWithFlags(&sB, cudaStreamNonBlocking);
        cudaEventCreateWithFlags(&eF, cudaEventDisableTiming);
        cudaEventCreateWithFlags(&eA, cudaEventDisableTiming);
        cudaEventCreateWithFlags(&eB, cudaEventDisableTiming);
    }

    cudaEventRecord(eF, 0);
    cudaStreamWaitEvent(sA, eF, 0);

    // stream A: weight prep (transpose + tf32 packs)
    k_prep<<<3936, 256, 0, sA>>>(mgru_wih, mgru_whh, vgru_wih, vgru_whh);
    cudaEventRecord(eA, sA);

    // stream B: visit embeddings + xg for keys 0-2 (needs transposed WIH_M)
    cudaStreamWaitEvent(sB, eA, 0);
    k_embed_xg012<<<dim3(256, 3), 384, 0, sB>>>(tok_cond, tok_proc, tok_drug,
                                                emb_cond, emb_proc, emb_drug, mgru_bih);
    cudaEventRecord(eB, sB);

    // main stream: monitor chain
    k_embed_mon<<<dim3(2048, 2), 128>>>(tok_lab_item, tok_lab_value,
                                        tok_inj_item, tok_inj_value,
                                        emb_li, emb_lv, emb_ii, emb_iv);
    cudaStreamWaitEvent(0, eA, 0);
    k_xg34_mma<<<dim3(128, 2), 256>>>(mgru_bih);
    cudaStreamWaitEvent(0, eB, 0);
    k_mon_gru<<<dim3(16, 5), 512, 230144>>>(mgru_bhh);
    k_vxg_vis<<<dim3(16, 7), 384, 223488>>>(weight, age, info_w, info_b,
                                            vgru_bih, vgru_bhh);
    k_fc<<<16, 256>>>(fc_w, fc_b, out);
}